// round 1
// baseline (speedup 1.0000x reference)
#include <cuda_runtime.h>
#include <math.h>

// Problem constants
#define BN_POS 2048      // B*N = 4*512
#define MDIM   32768
#define DDIM   1024
#define KSEL   32

// Scratch (device globals; no allocation allowed)
__device__ float g_c[MDIM];
__device__ int   g_sel[2][KSEL];            // [0]=pos (top-32 desc), [1]=neg (bottom-32 asc)
__device__ float g_kproj[2][KSEL][DDIM];
__device__ float g_vproj[2][KSEL][DDIM];
__device__ float g_q[(size_t)BN_POS * DDIM];
__device__ int   g_sign[BN_POS];            // 0 -> pos list, 1 -> neg list
__device__ float g_ctx[(size_t)BN_POS * DDIM];

// ---------------------------------------------------------------------------
// Kernel 1: c[m] = sum(keys[m]) / (sqrt(D) * ||keys[m]||)
// ---------------------------------------------------------------------------
__global__ void __launch_bounds__(256) compute_c_kernel(const float* __restrict__ keys) {
    int warp = threadIdx.x >> 5;
    int lane = threadIdx.x & 31;
    int row  = blockIdx.x * 8 + warp;
    const float4* kp = reinterpret_cast<const float4*>(keys + (size_t)row * DDIM);
    float s = 0.f, ss = 0.f;
#pragma unroll
    for (int i = 0; i < 8; i++) {
        float4 v = kp[lane + i * 32];
        s  += (v.x + v.y) + (v.z + v.w);
        ss += v.x * v.x + v.y * v.y + v.z * v.z + v.w * v.w;
    }
#pragma unroll
    for (int o = 16; o > 0; o >>= 1) {
        s  += __shfl_xor_sync(0xffffffffu, s, o);
        ss += __shfl_xor_sync(0xffffffffu, ss, o);
    }
    if (lane == 0) g_c[row] = s / (32.0f * sqrtf(ss));
}

// ---------------------------------------------------------------------------
// Kernel 2: top-32 (desc) and bottom-32 (asc) of c, jax.top_k tie semantics
// (higher value first; equal values -> lower index first). Single block,
// values held in registers, iterative arg-extreme with incremental rescan.
// ---------------------------------------------------------------------------
__global__ void __launch_bounds__(1024) select_kernel() {
    __shared__ float swv[32];
    __shared__ int   swi[32];
    __shared__ int   s_wi;
    const int tid  = threadIdx.x;
    const int lane = tid & 31, warp = tid >> 5;

    float v[32];

    for (int phase = 0; phase < 2; phase++) {
#pragma unroll
        for (int k = 0; k < 32; k++) v[k] = g_c[k * 1024 + tid];

        // local best (strict compare keeps smallest k => smallest global index on ties)
        float bv = v[0]; int bk = 0;
#pragma unroll
        for (int k = 1; k < 32; k++) {
            bool b = (phase == 0) ? (v[k] > bv) : (v[k] < bv);
            if (b) { bv = v[k]; bk = k; }
        }

        for (int r = 0; r < KSEL; r++) {
            float cv = bv; int ci = bk * 1024 + tid;
#pragma unroll
            for (int o = 16; o > 0; o >>= 1) {
                float ov = __shfl_xor_sync(0xffffffffu, cv, o);
                int   oi = __shfl_xor_sync(0xffffffffu, ci, o);
                bool b = (phase == 0) ? ((ov > cv) || (ov == cv && oi < ci))
                                      : ((ov < cv) || (ov == cv && oi < ci));
                if (b) { cv = ov; ci = oi; }
            }
            if (lane == 0) { swv[warp] = cv; swi[warp] = ci; }
            __syncthreads();
            if (warp == 0) {
                cv = swv[lane]; ci = swi[lane];
#pragma unroll
                for (int o = 16; o > 0; o >>= 1) {
                    float ov = __shfl_xor_sync(0xffffffffu, cv, o);
                    int   oi = __shfl_xor_sync(0xffffffffu, ci, o);
                    bool b = (phase == 0) ? ((ov > cv) || (ov == cv && oi < ci))
                                          : ((ov < cv) || (ov == cv && oi < ci));
                    if (b) { cv = ov; ci = oi; }
                }
                if (lane == 0) { s_wi = ci; g_sel[phase][r] = ci; }
            }
            __syncthreads();
            int wi = s_wi;
            if ((wi & 1023) == tid) {
                int wk = wi >> 10;
#pragma unroll
                for (int k = 0; k < 32; k++)
                    if (k == wk) v[k] = (phase == 0) ? -INFINITY : INFINITY;
                bv = v[0]; bk = 0;
#pragma unroll
                for (int k = 1; k < 32; k++) {
                    bool b = (phase == 0) ? (v[k] > bv) : (v[k] < bv);
                    if (b) { bv = v[k]; bk = k; }
                }
            }
            __syncthreads();
        }
    }
}

// ---------------------------------------------------------------------------
// Kernel 3: fp32 NT GEMM using packed fma.rn.f32x2 (FFMA2, PTX-only path).
// C[i,j] = sum_k A[i,k]*B[j,k] (+bias[j]). 128x128x16 tile, 256 thr, 8x8/thr.
// ---------------------------------------------------------------------------
__global__ void __launch_bounds__(256) sgemm_nt(const float* __restrict__ A,
                                                const float* __restrict__ B,
                                                float* __restrict__ C,
                                                const float* __restrict__ bias,
                                                int Md, int Nd, int Kd) {
    __shared__ float As2[16][256];   // A values duplicated: [k][2m]=[k][2m+1]=A
    __shared__ float Bs[16][128];
    const int tid = threadIdx.x;
    const int tx = tid & 15;   // -> n
    const int ty = tid >> 4;   // -> m
    const int tm0 = blockIdx.y * 128;
    const int tn0 = blockIdx.x * 128;

    unsigned long long acc[8][4];
#pragma unroll
    for (int i = 0; i < 8; i++)
#pragma unroll
        for (int j = 0; j < 4; j++) acc[i][j] = 0ull;

    for (int k0 = 0; k0 < Kd; k0 += 16) {
#pragma unroll
        for (int t = 0; t < 2; t++) {
            int e = tid + t * 256;        // 0..511
            int row = e >> 2;
            int kc  = (e & 3) << 2;
            float4 a = *reinterpret_cast<const float4*>(&A[(size_t)(tm0 + row) * Kd + k0 + kc]);
            *reinterpret_cast<float2*>(&As2[kc + 0][2 * row]) = make_float2(a.x, a.x);
            *reinterpret_cast<float2*>(&As2[kc + 1][2 * row]) = make_float2(a.y, a.y);
            *reinterpret_cast<float2*>(&As2[kc + 2][2 * row]) = make_float2(a.z, a.z);
            *reinterpret_cast<float2*>(&As2[kc + 3][2 * row]) = make_float2(a.w, a.w);
            float4 b = *reinterpret_cast<const float4*>(&B[(size_t)(tn0 + row) * Kd + k0 + kc]);
            Bs[kc + 0][row] = b.x; Bs[kc + 1][row] = b.y;
            Bs[kc + 2][row] = b.z; Bs[kc + 3][row] = b.w;
        }
        __syncthreads();
#pragma unroll
        for (int k = 0; k < 16; k++) {
            unsigned long long a2[8], b2[4];
#pragma unroll
            for (int i = 0; i < 8; i++)
                a2[i] = *reinterpret_cast<const unsigned long long*>(&As2[k][(ty * 8 + i) * 2]);
#pragma unroll
            for (int j = 0; j < 4; j++)
                b2[j] = *reinterpret_cast<const unsigned long long*>(&Bs[k][tx * 8 + j * 2]);
#pragma unroll
            for (int i = 0; i < 8; i++)
#pragma unroll
                for (int j = 0; j < 4; j++)
                    asm("fma.rn.f32x2 %0, %1, %2, %0;"
                        : "+l"(acc[i][j]) : "l"(a2[i]), "l"(b2[j]));
        }
        __syncthreads();
    }

#pragma unroll
    for (int i = 0; i < 8; i++) {
        int r = tm0 + ty * 8 + i;
        int cbase = tn0 + tx * 8;
        float o[8];
#pragma unroll
        for (int j = 0; j < 4; j++) {
            unsigned long long u = acc[i][j];
            o[2 * j]     = __uint_as_float((unsigned)(u & 0xffffffffu));
            o[2 * j + 1] = __uint_as_float((unsigned)(u >> 32));
        }
        if (bias) {
#pragma unroll
            for (int j = 0; j < 8; j++) o[j] += bias[cbase + j];
        }
        *reinterpret_cast<float4*>(&C[(size_t)r * Nd + cbase])     = make_float4(o[0], o[1], o[2], o[3]);
        *reinterpret_cast<float4*>(&C[(size_t)r * Nd + cbase + 4]) = make_float4(o[4], o[5], o[6], o[7]);
    }
}

// ---------------------------------------------------------------------------
// Kernel 4: sign of qm (mean of q_full row) per position
// ---------------------------------------------------------------------------
__global__ void __launch_bounds__(256) sign_kernel() {
    int row = blockIdx.x;
    const float4* q = reinterpret_cast<const float4*>(g_q + (size_t)row * DDIM);
    float4 v = q[threadIdx.x];
    float s = (v.x + v.y) + (v.z + v.w);
    __shared__ float red[8];
    int lane = threadIdx.x & 31, w = threadIdx.x >> 5;
#pragma unroll
    for (int o = 16; o > 0; o >>= 1) s += __shfl_xor_sync(0xffffffffu, s, o);
    if (lane == 0) red[w] = s;
    __syncthreads();
    if (threadIdx.x == 0) {
        float t = 0.f;
#pragma unroll
        for (int i = 0; i < 8; i++) t += red[i];
        g_sign[row] = (t >= 0.f) ? 0 : 1;
    }
}

// ---------------------------------------------------------------------------
// Kernel 5: K/V projections for the two candidate selections.
// dst[sel][slot][o] = sum_d src[selidx][d] * W[o][d].  grid (8 coltiles, 2 sel, 2 mat)
// ---------------------------------------------------------------------------
__global__ void __launch_bounds__(256) kvproj_kernel(const float* __restrict__ keys,
                                                     const float* __restrict__ vals,
                                                     const float* __restrict__ Wk,
                                                     const float* __restrict__ Wv) {
    __shared__ float As[32][64];
    __shared__ float Bs[64][132];
    __shared__ int sidx[32];
    const int tid = threadIdx.x;
    const int ct  = blockIdx.x;
    const int sel = blockIdx.y;
    const int mat = blockIdx.z;
    const float* src = mat ? vals : keys;
    const float* W   = mat ? Wv : Wk;
    float* dst = mat ? &g_vproj[sel][0][0] : &g_kproj[sel][0][0];
    if (tid < 32) sidx[tid] = g_sel[sel][tid];
    __syncthreads();
    const int tx = tid & 15, ty = tid >> 4;
    const int col0 = ct * 128;
    float acc0[8] = {}, acc1[8] = {};
    for (int kk = 0; kk < DDIM; kk += 64) {
#pragma unroll
        for (int t = 0; t < 2; t++) {
            int e = tid + t * 256;
            int slot = e >> 4, f4 = e & 15;
            *reinterpret_cast<float4*>(&As[slot][f4 * 4]) =
                *reinterpret_cast<const float4*>(&src[(size_t)sidx[slot] * DDIM + kk + f4 * 4]);
        }
#pragma unroll
        for (int t = 0; t < 8; t++) {
            int e = tid + t * 256;
            int col = e >> 4, f4 = e & 15;
            float4 v = *reinterpret_cast<const float4*>(&W[(size_t)(col0 + col) * DDIM + kk + f4 * 4]);
            Bs[f4 * 4 + 0][col] = v.x; Bs[f4 * 4 + 1][col] = v.y;
            Bs[f4 * 4 + 2][col] = v.z; Bs[f4 * 4 + 3][col] = v.w;
        }
        __syncthreads();
#pragma unroll
        for (int k = 0; k < 64; k++) {
            float a0 = As[ty][k], a1 = As[ty + 16][k];
#pragma unroll
            for (int j = 0; j < 8; j++) {
                float b = Bs[k][tx * 8 + j];
                acc0[j] = fmaf(a0, b, acc0[j]);
                acc1[j] = fmaf(a1, b, acc1[j]);
            }
        }
        __syncthreads();
    }
#pragma unroll
    for (int j = 0; j < 8; j += 4) {
        *reinterpret_cast<float4*>(&dst[(size_t)ty * DDIM + col0 + tx * 8 + j]) =
            make_float4(acc0[j], acc0[j + 1], acc0[j + 2], acc0[j + 3]);
        *reinterpret_cast<float4*>(&dst[(size_t)(ty + 16) * DDIM + col0 + tx * 8 + j]) =
            make_float4(acc1[j], acc1[j + 1], acc1[j + 2], acc1[j + 3]);
    }
}

// ---------------------------------------------------------------------------
// Kernel 6: attention. 16 positions per block, loop over 16 heads, per-head
// K/V slices (32x64) in smem. Writes ctx, avg_attn, sel_idx.
// ---------------------------------------------------------------------------
__global__ void __launch_bounds__(256) attn_kernel(float* __restrict__ out_attn,
                                                   float* __restrict__ out_selidx) {
    __shared__ float qs[16][68];
    __shared__ float Kh[32][65];
    __shared__ float Vh[32][65];
    __shared__ float sc[16][33];
    __shared__ float aacc[16][32];
    __shared__ int ssel[16];
    const int tid = threadIdx.x;
    const int p0 = blockIdx.x * 16;
    if (tid < 16) ssel[tid] = g_sign[p0 + tid];
#pragma unroll
    for (int t = 0; t < 2; t++) {
        int i = tid + t * 256;
        aacc[i >> 5][i & 31] = 0.f;
    }
    __syncthreads();
    int use0 = 0, use1 = 0;
#pragma unroll
    for (int p = 0; p < 16; p++) { if (ssel[p]) use1++; else use0++; }

    for (int h = 0; h < 16; h++) {
        {   // load q slice for this head: 16 pos x 64
            int pos = tid >> 4, f4 = tid & 15;
            float4 v = *reinterpret_cast<const float4*>(&g_q[(size_t)(p0 + pos) * DDIM + h * 64 + f4 * 4]);
            qs[pos][f4 * 4 + 0] = v.x; qs[pos][f4 * 4 + 1] = v.y;
            qs[pos][f4 * 4 + 2] = v.z; qs[pos][f4 * 4 + 3] = v.w;
        }
        for (int sel = 0; sel < 2; sel++) {
            if (sel == 0 ? (use0 == 0) : (use1 == 0)) continue;
#pragma unroll
            for (int t = 0; t < 2; t++) {
                int e = tid + t * 256;
                int slot = e >> 4, f4 = e & 15;
                float4 kv = *reinterpret_cast<const float4*>(&g_kproj[sel][slot][h * 64 + f4 * 4]);
                Kh[slot][f4 * 4 + 0] = kv.x; Kh[slot][f4 * 4 + 1] = kv.y;
                Kh[slot][f4 * 4 + 2] = kv.z; Kh[slot][f4 * 4 + 3] = kv.w;
                float4 vv = *reinterpret_cast<const float4*>(&g_vproj[sel][slot][h * 64 + f4 * 4]);
                Vh[slot][f4 * 4 + 0] = vv.x; Vh[slot][f4 * 4 + 1] = vv.y;
                Vh[slot][f4 * 4 + 2] = vv.z; Vh[slot][f4 * 4 + 3] = vv.w;
            }
            __syncthreads();
            // scores
#pragma unroll
            for (int t = 0; t < 2; t++) {
                int idx = tid + t * 256;
                int pos = idx >> 5, slot = idx & 31;
                if (ssel[pos] == sel) {
                    float s = 0.f;
#pragma unroll
                    for (int k = 0; k < 64; k++) s = fmaf(qs[pos][k], Kh[slot][k], s);
                    sc[pos][slot] = s * 0.125f;
                }
            }
            __syncthreads();
            // softmax per (pos) row over 32 slots; warp handles rows w, w+8
            {
                int w = tid >> 5, lane = tid & 31;
#pragma unroll
                for (int t = 0; t < 2; t++) {
                    int pos = w + t * 8;
                    if (ssel[pos] == sel) {
                        float vsc = sc[pos][lane];
                        float mx = vsc;
#pragma unroll
                        for (int o = 16; o > 0; o >>= 1)
                            mx = fmaxf(mx, __shfl_xor_sync(0xffffffffu, mx, o));
                        float e = expf(vsc - mx);
                        float sm = e;
#pragma unroll
                        for (int o = 16; o > 0; o >>= 1)
                            sm += __shfl_xor_sync(0xffffffffu, sm, o);
                        float a = e / sm;
                        sc[pos][lane] = a;
                        aacc[pos][lane] += a * 0.0625f;  // 1/16 heads
                    }
                }
            }
            __syncthreads();
            // ctx
#pragma unroll
            for (int t = 0; t < 4; t++) {
                int idx = tid + t * 256;
                int pos = idx >> 6, e = idx & 63;
                if (ssel[pos] == sel) {
                    float s = 0.f;
#pragma unroll
                    for (int slot = 0; slot < 32; slot++)
                        s = fmaf(sc[pos][slot], Vh[slot][e], s);
                    g_ctx[(size_t)(p0 + pos) * DDIM + h * 64 + e] = s;
                }
            }
            __syncthreads();
        }
    }
    // outputs
#pragma unroll
    for (int t = 0; t < 2; t++) {
        int idx = tid + t * 256;
        int pos = idx >> 5, slot = idx & 31;
        if (out_attn)
            out_attn[(size_t)(p0 + pos) * KSEL + slot] = aacc[pos][slot];
        if (out_selidx)
            out_selidx[(size_t)(p0 + pos) * KSEL + slot] = (float)g_sel[ssel[pos]][slot];
    }
}

// ---------------------------------------------------------------------------
// Kernel 7: LayerNorm in-place on d_out rows (biased variance)
// ---------------------------------------------------------------------------
__global__ void __launch_bounds__(256) ln_kernel(float* __restrict__ io,
                                                 const float* __restrict__ gamma,
                                                 const float* __restrict__ beta) {
    int row = blockIdx.x;
    float4* p = reinterpret_cast<float4*>(io + (size_t)row * DDIM);
    float4 v = p[threadIdx.x];
    float s  = (v.x + v.y) + (v.z + v.w);
    float ss = v.x * v.x + v.y * v.y + v.z * v.z + v.w * v.w;
    __shared__ float r1[8], r2[8];
    __shared__ float fmu, frs;
    int lane = threadIdx.x & 31, w = threadIdx.x >> 5;
#pragma unroll
    for (int o = 16; o > 0; o >>= 1) {
        s  += __shfl_xor_sync(0xffffffffu, s, o);
        ss += __shfl_xor_sync(0xffffffffu, ss, o);
    }
    if (lane == 0) { r1[w] = s; r2[w] = ss; }
    __syncthreads();
    if (threadIdx.x == 0) {
        float ts = 0.f, tss = 0.f;
#pragma unroll
        for (int i = 0; i < 8; i++) { ts += r1[i]; tss += r2[i]; }
        float mu  = ts * (1.f / 1024.f);
        float var = tss * (1.f / 1024.f) - mu * mu;
        fmu = mu;
        frs = rsqrtf(var + 1e-5f);
    }
    __syncthreads();
    float mu = fmu, rstd = frs;
    const float4 g = reinterpret_cast<const float4*>(gamma)[threadIdx.x];
    const float4 b = reinterpret_cast<const float4*>(beta)[threadIdx.x];
    v.x = (v.x - mu) * rstd * g.x + b.x;
    v.y = (v.y - mu) * rstd * g.y + b.y;
    v.z = (v.z - mu) * rstd * g.z + b.z;
    v.w = (v.w - mu) * rstd * g.w + b.w;
    p[threadIdx.x] = v;
}

// ---------------------------------------------------------------------------
extern "C" void kernel_launch(void* const* d_in, const int* in_sizes, int n_in,
                              void* d_out, int out_size) {
    const float* X     = (const float*)d_in[0];  // [2048,1024]
    const float* keys  = (const float*)d_in[1];  // [32768,1024]
    const float* vals  = (const float*)d_in[2];
    const float* Wq    = (const float*)d_in[3];
    const float* Wk    = (const float*)d_in[4];
    const float* Wv    = (const float*)d_in[5];
    const float* Wo    = (const float*)d_in[6];
    const float* bo    = (const float*)d_in[7];
    const float* gamma = (const float*)d_in[8];
    const float* beta  = (const float*)d_in[9];

    float* out = (float*)d_out;
    float* out_attn = nullptr;
    float* out_sel  = nullptr;
    const long long base = (long long)BN_POS * DDIM;
    if ((long long)out_size >= base + (long long)BN_POS * KSEL)
        out_attn = out + base;
    if ((long long)out_size >= base + 2LL * BN_POS * KSEL)
        out_sel = out + base + (long long)BN_POS * KSEL;

    void *pq = nullptr, *pctx = nullptr;
    cudaGetSymbolAddress(&pq, g_q);
    cudaGetSymbolAddress(&pctx, g_ctx);

    // 1. memory-key statistics
    compute_c_kernel<<<MDIM / 8, 256>>>(keys);
    // 2. the two candidate top-k sets
    select_kernel<<<1, 1024>>>();
    // 3. q projection  (q_full = X @ Wq^T)
    sgemm_nt<<<dim3(DDIM / 128, BN_POS / 128), 256>>>(X, Wq, (float*)pq, nullptr,
                                                      BN_POS, DDIM, DDIM);
    // 4. sign(qm) per position
    sign_kernel<<<BN_POS, 256>>>();
    // 5. K/V projections of the two selections
    kvproj_kernel<<<dim3(8, 2, 2), 256>>>(keys, vals, Wk, Wv);
    // 6. attention -> ctx, avg_attn, sel_idx
    attn_kernel<<<BN_POS / 16, 256>>>(out_attn, out_sel);
    // 7. output projection (+bias)
    sgemm_nt<<<dim3(DDIM / 128, BN_POS / 128), 256>>>((const float*)pctx, Wo, out, bo,
                                                      BN_POS, DDIM, DDIM);
    // 8. layernorm in-place
    ln_kernel<<<BN_POS, 256>>>(out, gamma, beta);
}

// round 3
// speedup vs baseline: 1.4267x; 1.4267x over previous
#include <cuda_runtime.h>
#include <cuda_bf16.h>
#include <math.h>
#include <cstdint>

// Problem constants
#define BN_POS 2048      // B*N = 4*512
#define MDIM   32768
#define DDIM   1024
#define KSEL   32
#define GK     3072      // split-K: A=[hi|hi|lo], B(W)=[hi|lo|hi]
#define BK     32
#define NKIT   (GK / BK) // 96

// Scratch (device globals; no allocation allowed)
__device__ float g_c[MDIM];
__device__ int   g_sel[2][KSEL];
__device__ float g_kproj[2][KSEL][DDIM];
__device__ float g_vproj[2][KSEL][DDIM];
__device__ float g_q[(size_t)BN_POS * DDIM];
__device__ int   g_sign[BN_POS];
__device__ float g_ctx[(size_t)BN_POS * DDIM];
__device__ __nv_bfloat16 g_As[(size_t)BN_POS * GK];   // split activations
__device__ __nv_bfloat16 g_Ws[2][(size_t)DDIM * GK];  // split Wq, Wo

// ---------------------------------------------------------------------------
// bf16-split GEMM via mma.sync (HMMA) + ldmatrix + cp.async double buffer.
// C[m][n] = sum_k A[m][k]*B[n][k] (+bias[n]).  M=2048, N=1024, K=GK.
// CTA 128x128, 8 warps (2x4), warp tile 64x32.
// ---------------------------------------------------------------------------
#define SSTRIDE 40   // padded row stride in elems (80B: 16B-aligned, conflict-free)

__global__ void __launch_bounds__(256) gemm_mma_kernel(
    const __nv_bfloat16* __restrict__ A,
    const __nv_bfloat16* __restrict__ Bm,
    float* __restrict__ C,
    const float* __restrict__ bias) {
    __shared__ __align__(16) __nv_bfloat16 As[2][128][SSTRIDE];
    __shared__ __align__(16) __nv_bfloat16 Bs[2][128][SSTRIDE];

    const int tid = threadIdx.x;
    const int wid = tid >> 5, lane = tid & 31;
    const int wm = wid >> 2, wn = wid & 3;     // warp grid 2 x 4
    const int tn0 = blockIdx.x * 128;
    const int tm0 = blockIdx.y * 128;

    const __nv_bfloat16* Ag = A + (size_t)tm0 * GK;
    const __nv_bfloat16* Bg = Bm + (size_t)tn0 * GK;

    const uint32_t smA = (uint32_t)__cvta_generic_to_shared(&As[0][0][0]);
    const uint32_t smB = (uint32_t)__cvta_generic_to_shared(&Bs[0][0][0]);

    float acc[4][4][4];
#pragma unroll
    for (int i = 0; i < 4; i++)
#pragma unroll
        for (int j = 0; j < 4; j++)
#pragma unroll
            for (int r = 0; r < 4; r++) acc[i][j][r] = 0.f;

    // cp.async loader: 512 16B chunks for A + 512 for B per stage; 4 per thread
    auto load_stage = [&](int it, int buf) {
        const int k0 = it * BK;
#pragma unroll
        for (int t = 0; t < 4; t++) {
            int ee = tid + t * 256;
            int row = (ee & 511) >> 2;
            int seg = ee & 3;                  // 8-elem (16B) segment
            const __nv_bfloat16* gp;
            uint32_t sp;
            if (ee < 512) {
                gp = Ag + (size_t)row * GK + k0 + seg * 8;
                sp = smA + (uint32_t)(((buf * 128 + row) * SSTRIDE + seg * 8) * 2);
            } else {
                gp = Bg + (size_t)row * GK + k0 + seg * 8;
                sp = smB + (uint32_t)(((buf * 128 + row) * SSTRIDE + seg * 8) * 2);
            }
            asm volatile("cp.async.cg.shared.global [%0], [%1], 16;"
                         :: "r"(sp), "l"(gp));
        }
        asm volatile("cp.async.commit_group;" ::: "memory");
    };

    load_stage(0, 0);

    for (int it = 0; it < NKIT; it++) {
        const int buf = it & 1;
        if (it + 1 < NKIT) {
            load_stage(it + 1, (it + 1) & 1);
            asm volatile("cp.async.wait_group 1;" ::: "memory");
        } else {
            asm volatile("cp.async.wait_group 0;" ::: "memory");
        }
        __syncthreads();

#pragma unroll
        for (int ks = 0; ks < 2; ks++) {
            const int kb = ks * 16;
            uint32_t a[4][4], b[4][2];
            const int mat = lane >> 3, r8 = lane & 7;
#pragma unroll
            for (int mt = 0; mt < 4; mt++) {
                int row = wm * 64 + mt * 16 + (mat & 1) * 8 + r8;
                int col = kb + (mat >> 1) * 8;
                uint32_t ad = smA + (uint32_t)(((buf * 128 + row) * SSTRIDE + col) * 2);
                asm volatile(
                    "ldmatrix.sync.aligned.m8n8.x4.shared.b16 {%0,%1,%2,%3}, [%4];"
                    : "=r"(a[mt][0]), "=r"(a[mt][1]), "=r"(a[mt][2]), "=r"(a[mt][3])
                    : "r"(ad));
            }
#pragma unroll
            for (int p = 0; p < 2; p++) {
                int nrow = wn * 32 + p * 16 + (mat >> 1) * 8 + r8;
                int col = kb + (mat & 1) * 8;
                uint32_t bd = smB + (uint32_t)(((buf * 128 + nrow) * SSTRIDE + col) * 2);
                uint32_t q0, q1, q2, q3;
                asm volatile(
                    "ldmatrix.sync.aligned.m8n8.x4.shared.b16 {%0,%1,%2,%3}, [%4];"
                    : "=r"(q0), "=r"(q1), "=r"(q2), "=r"(q3)
                    : "r"(bd));
                b[2 * p][0] = q0; b[2 * p][1] = q1;
                b[2 * p + 1][0] = q2; b[2 * p + 1][1] = q3;
            }
#pragma unroll
            for (int mt = 0; mt < 4; mt++)
#pragma unroll
                for (int nt = 0; nt < 4; nt++) {
                    asm volatile(
                        "mma.sync.aligned.m16n8k16.row.col.f32.bf16.bf16.f32 "
                        "{%0,%1,%2,%3}, {%4,%5,%6,%7}, {%8,%9}, {%0,%1,%2,%3};"
                        : "+f"(acc[mt][nt][0]), "+f"(acc[mt][nt][1]),
                          "+f"(acc[mt][nt][2]), "+f"(acc[mt][nt][3])
                        : "r"(a[mt][0]), "r"(a[mt][1]), "r"(a[mt][2]), "r"(a[mt][3]),
                          "r"(b[nt][0]), "r"(b[nt][1]));
                }
        }
        __syncthreads();
    }

    // epilogue: c0,c1 -> (row, col..col+1); c2,c3 -> (row+8, ...)
    const int rl = lane >> 2, cl = (lane & 3) * 2;
#pragma unroll
    for (int mt = 0; mt < 4; mt++) {
        int row = tm0 + wm * 64 + mt * 16 + rl;
#pragma unroll
        for (int nt = 0; nt < 4; nt++) {
            int col = tn0 + wn * 32 + nt * 8 + cl;
            float b0 = 0.f, b1 = 0.f;
            if (bias) { b0 = bias[col]; b1 = bias[col + 1]; }
            *(float2*)(C + (size_t)row * 1024 + col) =
                make_float2(acc[mt][nt][0] + b0, acc[mt][nt][1] + b1);
            *(float2*)(C + (size_t)(row + 8) * 1024 + col) =
                make_float2(acc[mt][nt][2] + b0, acc[mt][nt][3] + b1);
        }
    }
}

// ---------------------------------------------------------------------------
// Split fp32 -> bf16 hi/lo.  act=1: [hi|hi|lo]   act=0 (weight): [hi|lo|hi]
// ---------------------------------------------------------------------------
__global__ void __launch_bounds__(256) split_kernel(const float* __restrict__ in,
                                                    __nv_bfloat16* __restrict__ out,
                                                    int act) {
    size_t idx = ((size_t)blockIdx.x * 256 + threadIdx.x) * 4;
    int row = (int)(idx >> 10);
    int k = (int)(idx & 1023);
    float4 v = *(const float4*)(in + idx);
    __nv_bfloat16 h0 = __float2bfloat16_rn(v.x), h1 = __float2bfloat16_rn(v.y);
    __nv_bfloat16 h2 = __float2bfloat16_rn(v.z), h3 = __float2bfloat16_rn(v.w);
    __nv_bfloat16 l0 = __float2bfloat16_rn(v.x - __bfloat162float(h0));
    __nv_bfloat16 l1 = __float2bfloat16_rn(v.y - __bfloat162float(h1));
    __nv_bfloat16 l2 = __float2bfloat16_rn(v.z - __bfloat162float(h2));
    __nv_bfloat16 l3 = __float2bfloat16_rn(v.w - __bfloat162float(h3));
    __nv_bfloat162 hA = __nv_bfloat162(h0, h1), hB = __nv_bfloat162(h2, h3);
    __nv_bfloat162 lA = __nv_bfloat162(l0, l1), lB = __nv_bfloat162(l2, l3);
    __nv_bfloat162* o0 = (__nv_bfloat162*)(out + (size_t)row * GK + k);
    __nv_bfloat162* o1 = (__nv_bfloat162*)(out + (size_t)row * GK + 1024 + k);
    __nv_bfloat162* o2 = (__nv_bfloat162*)(out + (size_t)row * GK + 2048 + k);
    o0[0] = hA; o0[1] = hB;
    if (act) { o1[0] = hA; o1[1] = hB; o2[0] = lA; o2[1] = lB; }
    else     { o1[0] = lA; o1[1] = lB; o2[0] = hA; o2[1] = hB; }
}

// ---------------------------------------------------------------------------
// Kernel 1: c[m] = sum(keys[m]) / (sqrt(D) * ||keys[m]||)
// ---------------------------------------------------------------------------
__global__ void __launch_bounds__(256) compute_c_kernel(const float* __restrict__ keys) {
    int warp = threadIdx.x >> 5;
    int lane = threadIdx.x & 31;
    int row  = blockIdx.x * 8 + warp;
    const float4* kp = reinterpret_cast<const float4*>(keys + (size_t)row * DDIM);
    float s = 0.f, ss = 0.f;
#pragma unroll
    for (int i = 0; i < 8; i++) {
        float4 v = kp[lane + i * 32];
        s  += (v.x + v.y) + (v.z + v.w);
        ss += v.x * v.x + v.y * v.y + v.z * v.z + v.w * v.w;
    }
#pragma unroll
    for (int o = 16; o > 0; o >>= 1) {
        s  += __shfl_xor_sync(0xffffffffu, s, o);
        ss += __shfl_xor_sync(0xffffffffu, ss, o);
    }
    if (lane == 0) g_c[row] = s / (32.0f * sqrtf(ss));
}

// ---------------------------------------------------------------------------
// Kernel 2: top-32 (desc) and bottom-32 (asc) of c, jax.top_k tie semantics
// ---------------------------------------------------------------------------
__global__ void __launch_bounds__(1024) select_kernel() {
    __shared__ float swv[32];
    __shared__ int   swi[32];
    __shared__ int   s_wi;
    const int tid  = threadIdx.x;
    const int lane = tid & 31, warp = tid >> 5;

    float v[32];

    for (int phase = 0; phase < 2; phase++) {
#pragma unroll
        for (int k = 0; k < 32; k++) v[k] = g_c[k * 1024 + tid];

        float bv = v[0]; int bk = 0;
#pragma unroll
        for (int k = 1; k < 32; k++) {
            bool b = (phase == 0) ? (v[k] > bv) : (v[k] < bv);
            if (b) { bv = v[k]; bk = k; }
        }

        for (int r = 0; r < KSEL; r++) {
            float cv = bv; int ci = bk * 1024 + tid;
#pragma unroll
            for (int o = 16; o > 0; o >>= 1) {
                float ov = __shfl_xor_sync(0xffffffffu, cv, o);
                int   oi = __shfl_xor_sync(0xffffffffu, ci, o);
                bool b = (phase == 0) ? ((ov > cv) || (ov == cv && oi < ci))
                                      : ((ov < cv) || (ov == cv && oi < ci));
                if (b) { cv = ov; ci = oi; }
            }
            if (lane == 0) { swv[warp] = cv; swi[warp] = ci; }
            __syncthreads();
            if (warp == 0) {
                cv = swv[lane]; ci = swi[lane];
#pragma unroll
                for (int o = 16; o > 0; o >>= 1) {
                    float ov = __shfl_xor_sync(0xffffffffu, cv, o);
                    int   oi = __shfl_xor_sync(0xffffffffu, ci, o);
                    bool b = (phase == 0) ? ((ov > cv) || (ov == cv && oi < ci))
                                          : ((ov < cv) || (ov == cv && oi < ci));
                    if (b) { cv = ov; ci = oi; }
                }
                if (lane == 0) { s_wi = ci; g_sel[phase][r] = ci; }
            }
            __syncthreads();
            int wi = s_wi;
            if ((wi & 1023) == tid) {
                int wk = wi >> 10;
#pragma unroll
                for (int k = 0; k < 32; k++)
                    if (k == wk) v[k] = (phase == 0) ? -INFINITY : INFINITY;
                bv = v[0]; bk = 0;
#pragma unroll
                for (int k = 1; k < 32; k++) {
                    bool b = (phase == 0) ? (v[k] > bv) : (v[k] < bv);
                    if (b) { bv = v[k]; bk = k; }
                }
            }
            __syncthreads();
        }
    }
}

// ---------------------------------------------------------------------------
// Kernel 4: sign of qm (mean of q_full row) per position
// ---------------------------------------------------------------------------
__global__ void __launch_bounds__(256) sign_kernel() {
    int row = blockIdx.x;
    const float4* q = reinterpret_cast<const float4*>(g_q + (size_t)row * DDIM);
    float4 v = q[threadIdx.x];
    float s = (v.x + v.y) + (v.z + v.w);
    __shared__ float red[8];
    int lane = threadIdx.x & 31, w = threadIdx.x >> 5;
#pragma unroll
    for (int o = 16; o > 0; o >>= 1) s += __shfl_xor_sync(0xffffffffu, s, o);
    if (lane == 0) red[w] = s;
    __syncthreads();
    if (threadIdx.x == 0) {
        float t = 0.f;
#pragma unroll
        for (int i = 0; i < 8; i++) t += red[i];
        g_sign[row] = (t >= 0.f) ? 0 : 1;
    }
}

// ---------------------------------------------------------------------------
// Kernel 5: K/V projections for the two candidate selections
// ---------------------------------------------------------------------------
__global__ void __launch_bounds__(256) kvproj_kernel(const float* __restrict__ keys,
                                                     const float* __restrict__ vals,
                                                     const float* __restrict__ Wk,
                                                     const float* __restrict__ Wv) {
    __shared__ float As[32][64];
    __shared__ float Bs[64][132];
    __shared__ int sidx[32];
    const int tid = threadIdx.x;
    const int ct  = blockIdx.x;
    const int sel = blockIdx.y;
    const int mat = blockIdx.z;
    const float* src = mat ? vals : keys;
    const float* W   = mat ? Wv : Wk;
    float* dst = mat ? &g_vproj[sel][0][0] : &g_kproj[sel][0][0];
    if (tid < 32) sidx[tid] = g_sel[sel][tid];
    __syncthreads();
    const int tx = tid & 15, ty = tid >> 4;
    const int col0 = ct * 128;
    float acc0[8] = {}, acc1[8] = {};
    for (int kk = 0; kk < DDIM; kk += 64) {
#pragma unroll
        for (int t = 0; t < 2; t++) {
            int e = tid + t * 256;
            int slot = e >> 4, f4 = e & 15;
            *reinterpret_cast<float4*>(&As[slot][f4 * 4]) =
                *reinterpret_cast<const float4*>(&src[(size_t)sidx[slot] * DDIM + kk + f4 * 4]);
        }
#pragma unroll
        for (int t = 0; t < 8; t++) {
            int e = tid + t * 256;
            int col = e >> 4, f4 = e & 15;
            float4 v = *reinterpret_cast<const float4*>(&W[(size_t)(col0 + col) * DDIM + kk + f4 * 4]);
            Bs[f4 * 4 + 0][col] = v.x; Bs[f4 * 4 + 1][col] = v.y;
            Bs[f4 * 4 + 2][col] = v.z; Bs[f4 * 4 + 3][col] = v.w;
        }
        __syncthreads();
#pragma unroll
        for (int k = 0; k < 64; k++) {
            float a0 = As[ty][k], a1 = As[ty + 16][k];
#pragma unroll
            for (int j = 0; j < 8; j++) {
                float b = Bs[k][tx * 8 + j];
                acc0[j] = fmaf(a0, b, acc0[j]);
                acc1[j] = fmaf(a1, b, acc1[j]);
            }
        }
        __syncthreads();
    }
#pragma unroll
    for (int j = 0; j < 8; j += 4) {
        *reinterpret_cast<float4*>(&dst[(size_t)ty * DDIM + col0 + tx * 8 + j]) =
            make_float4(acc0[j], acc0[j + 1], acc0[j + 2], acc0[j + 3]);
        *reinterpret_cast<float4*>(&dst[(size_t)(ty + 16) * DDIM + col0 + tx * 8 + j]) =
            make_float4(acc1[j], acc1[j + 1], acc1[j + 2], acc1[j + 3]);
    }
}

// ---------------------------------------------------------------------------
// Kernel 6: attention. 16 positions/block, loop over heads.
// ---------------------------------------------------------------------------
__global__ void __launch_bounds__(256) attn_kernel(float* __restrict__ out_attn,
                                                   float* __restrict__ out_selidx) {
    __shared__ float qs[16][68];
    __shared__ float Kh[32][65];
    __shared__ float Vh[32][65];
    __shared__ float sc[16][33];
    __shared__ float aacc[16][32];
    __shared__ int ssel[16];
    const int tid = threadIdx.x;
    const int p0 = blockIdx.x * 16;
    if (tid < 16) ssel[tid] = g_sign[p0 + tid];
#pragma unroll
    for (int t = 0; t < 2; t++) {
        int i = tid + t * 256;
        aacc[i >> 5][i & 31] = 0.f;
    }
    __syncthreads();
    int use0 = 0, use1 = 0;
#pragma unroll
    for (int p = 0; p < 16; p++) { if (ssel[p]) use1++; else use0++; }

    for (int h = 0; h < 16; h++) {
        {
            int pos = tid >> 4, f4 = tid & 15;
            float4 v = *reinterpret_cast<const float4*>(&g_q[(size_t)(p0 + pos) * DDIM + h * 64 + f4 * 4]);
            qs[pos][f4 * 4 + 0] = v.x; qs[pos][f4 * 4 + 1] = v.y;
            qs[pos][f4 * 4 + 2] = v.z; qs[pos][f4 * 4 + 3] = v.w;
        }
        for (int sel = 0; sel < 2; sel++) {
            if (sel == 0 ? (use0 == 0) : (use1 == 0)) continue;
#pragma unroll
            for (int t = 0; t < 2; t++) {
                int e = tid + t * 256;
                int slot = e >> 4, f4 = e & 15;
                float4 kv = *reinterpret_cast<const float4*>(&g_kproj[sel][slot][h * 64 + f4 * 4]);
                Kh[slot][f4 * 4 + 0] = kv.x; Kh[slot][f4 * 4 + 1] = kv.y;
                Kh[slot][f4 * 4 + 2] = kv.z; Kh[slot][f4 * 4 + 3] = kv.w;
                float4 vv = *reinterpret_cast<const float4*>(&g_vproj[sel][slot][h * 64 + f4 * 4]);
                Vh[slot][f4 * 4 + 0] = vv.x; Vh[slot][f4 * 4 + 1] = vv.y;
                Vh[slot][f4 * 4 + 2] = vv.z; Vh[slot][f4 * 4 + 3] = vv.w;
            }
            __syncthreads();
#pragma unroll
            for (int t = 0; t < 2; t++) {
                int idx = tid + t * 256;
                int pos = idx >> 5, slot = idx & 31;
                if (ssel[pos] == sel) {
                    float s = 0.f;
#pragma unroll
                    for (int k = 0; k < 64; k++) s = fmaf(qs[pos][k], Kh[slot][k], s);
                    sc[pos][slot] = s * 0.125f;
                }
            }
            __syncthreads();
            {
                int w = tid >> 5, lane = tid & 31;
#pragma unroll
                for (int t = 0; t < 2; t++) {
                    int pos = w + t * 8;
                    if (ssel[pos] == sel) {
                        float vsc = sc[pos][lane];
                        float mx = vsc;
#pragma unroll
                        for (int o = 16; o > 0; o >>= 1)
                            mx = fmaxf(mx, __shfl_xor_sync(0xffffffffu, mx, o));
                        float e = expf(vsc - mx);
                        float sm = e;
#pragma unroll
                        for (int o = 16; o > 0; o >>= 1)
                            sm += __shfl_xor_sync(0xffffffffu, sm, o);
                        float a = e / sm;
                        sc[pos][lane] = a;
                        aacc[pos][lane] += a * 0.0625f;
                    }
                }
            }
            __syncthreads();
#pragma unroll
            for (int t = 0; t < 4; t++) {
                int idx = tid + t * 256;
                int pos = idx >> 6, e = idx & 63;
                if (ssel[pos] == sel) {
                    float s = 0.f;
#pragma unroll
                    for (int slot = 0; slot < 32; slot++)
                        s = fmaf(sc[pos][slot], Vh[slot][e], s);
                    g_ctx[(size_t)(p0 + pos) * DDIM + h * 64 + e] = s;
                }
            }
            __syncthreads();
        }
    }
#pragma unroll
    for (int t = 0; t < 2; t++) {
        int idx = tid + t * 256;
        int pos = idx >> 5, slot = idx & 31;
        if (out_attn)
            out_attn[(size_t)(p0 + pos) * KSEL + slot] = aacc[pos][slot];
        if (out_selidx)
            out_selidx[(size_t)(p0 + pos) * KSEL + slot] = (float)g_sel[ssel[pos]][slot];
    }
}

// ---------------------------------------------------------------------------
// Kernel 7: LayerNorm in-place
// ---------------------------------------------------------------------------
__global__ void __launch_bounds__(256) ln_kernel(float* __restrict__ io,
                                                 const float* __restrict__ gamma,
                                                 const float* __restrict__ beta) {
    int row = blockIdx.x;
    float4* p = reinterpret_cast<float4*>(io + (size_t)row * DDIM);
    float4 v = p[threadIdx.x];
    float s  = (v.x + v.y) + (v.z + v.w);
    float ss = v.x * v.x + v.y * v.y + v.z * v.z + v.w * v.w;
    __shared__ float r1[8], r2[8];
    __shared__ float fmu, frs;
    int lane = threadIdx.x & 31, w = threadIdx.x >> 5;
#pragma unroll
    for (int o = 16; o > 0; o >>= 1) {
        s  += __shfl_xor_sync(0xffffffffu, s, o);
        ss += __shfl_xor_sync(0xffffffffu, ss, o);
    }
    if (lane == 0) { r1[w] = s; r2[w] = ss; }
    __syncthreads();
    if (threadIdx.x == 0) {
        float ts = 0.f, tss = 0.f;
#pragma unroll
        for (int i = 0; i < 8; i++) { ts += r1[i]; tss += r2[i]; }
        float mu  = ts * (1.f / 1024.f);
        float var = tss * (1.f / 1024.f) - mu * mu;
        fmu = mu;
        frs = rsqrtf(var + 1e-5f);
    }
    __syncthreads();
    float mu = fmu, rstd = frs;
    const float4 g = reinterpret_cast<const float4*>(gamma)[threadIdx.x];
    const float4 b = reinterpret_cast<const float4*>(beta)[threadIdx.x];
    v.x = (v.x - mu) * rstd * g.x + b.x;
    v.y = (v.y - mu) * rstd * g.y + b.y;
    v.z = (v.z - mu) * rstd * g.z + b.z;
    v.w = (v.w - mu) * rstd * g.w + b.w;
    p[threadIdx.x] = v;
}

// ---------------------------------------------------------------------------
extern "C" void kernel_launch(void* const* d_in, const int* in_sizes, int n_in,
                              void* d_out, int out_size) {
    const float* X     = (const float*)d_in[0];
    const float* keys  = (const float*)d_in[1];
    const float* vals  = (const float*)d_in[2];
    const float* Wq    = (const float*)d_in[3];
    const float* Wk    = (const float*)d_in[4];
    const float* Wv    = (const float*)d_in[5];
    const float* Wo    = (const float*)d_in[6];
    const float* bo    = (const float*)d_in[7];
    const float* gamma = (const float*)d_in[8];
    const float* beta  = (const float*)d_in[9];

    float* out = (float*)d_out;
    float* out_attn = nullptr;
    float* out_sel  = nullptr;
    const long long base = (long long)BN_POS * DDIM;
    if ((long long)out_size >= base + (long long)BN_POS * KSEL)
        out_attn = out + base;
    if ((long long)out_size >= base + 2LL * BN_POS * KSEL)
        out_sel = out + base + (long long)BN_POS * KSEL;

    void *pq = nullptr, *pctx = nullptr, *pAs = nullptr, *pWs = nullptr;
    cudaGetSymbolAddress(&pq, g_q);
    cudaGetSymbolAddress(&pctx, g_ctx);
    cudaGetSymbolAddress(&pAs, g_As);
    cudaGetSymbolAddress(&pWs, g_Ws);
    __nv_bfloat16* As = (__nv_bfloat16*)pAs;
    __nv_bfloat16* Ws0 = (__nv_bfloat16*)pWs;
    __nv_bfloat16* Ws1 = Ws0 + (size_t)DDIM * GK;

    // 1. memory-key statistics + candidate top-k sets
    compute_c_kernel<<<MDIM / 8, 256>>>(keys);
    select_kernel<<<1, 1024>>>();
    // 2. splits for q-proj
    split_kernel<<<(DDIM * DDIM) / 1024, 256>>>(Wq, Ws0, 0);
    split_kernel<<<(DDIM * DDIM) / 1024, 256>>>(Wo, Ws1, 0);
    split_kernel<<<(BN_POS * DDIM) / 1024, 256>>>(X, As, 1);
    // 3. q projection (HMMA)
    gemm_mma_kernel<<<dim3(8, 16), 256>>>(As, Ws0, (float*)pq, nullptr);
    // 4. sign(qm)
    sign_kernel<<<BN_POS, 256>>>();
    // 5. K/V projections of the two selections
    kvproj_kernel<<<dim3(8, 2, 2), 256>>>(keys, vals, Wk, Wv);
    // 6. attention
    attn_kernel<<<BN_POS / 16, 256>>>(out_attn, out_sel);
    // 7. split ctx, output projection (HMMA) + bias
    split_kernel<<<(BN_POS * DDIM) / 1024, 256>>>((const float*)pctx, As, 1);
    gemm_mma_kernel<<<dim3(8, 16), 256>>>(As, Ws1, out, bo);
    // 8. layernorm
    ln_kernel<<<BN_POS, 256>>>(out, gamma, beta);
}

// round 4
// speedup vs baseline: 1.4476x; 1.0147x over previous
#include <cuda_runtime.h>
#include <cuda_bf16.h>
#include <math.h>
#include <cstdint>

// Problem constants
#define BN_POS 2048      // B*N = 4*512
#define MDIM   32768
#define DDIM   1024
#define KSEL   32
#define GK     3072      // split-K: A=[hi|hi|lo], B(W)=[hi|lo|hi]
#define BK     32
#define NKIT   (GK / BK) // 96
#define STAGES 5

// Scratch (device globals; no allocation allowed)
__device__ float g_c[MDIM];
__device__ int   g_sel[2][KSEL];
__device__ float g_kproj[2][KSEL][DDIM];
__device__ float g_vproj[2][KSEL][DDIM];
__device__ float g_q[(size_t)BN_POS * DDIM];
__device__ int   g_sign[BN_POS];
__device__ float g_ctx[(size_t)BN_POS * DDIM];
__device__ float g_wpart[8][DDIM];
__device__ __nv_bfloat16 g_As[(size_t)BN_POS * GK];   // split activations
__device__ __nv_bfloat16 g_Ws[2][(size_t)DDIM * GK];  // split Wq, Wo

// ---------------------------------------------------------------------------
// bf16-split GEMM via mma.sync (HMMA) + ldmatrix + 5-stage cp.async pipeline.
// C[m][n] = sum_k A[m][k]*B[n][k] (+bias[n]).  M=2048, N=1024, K=GK.
// CTA 128x128, 8 warps (2x4), warp tile 64x32.
// ---------------------------------------------------------------------------
#define SSTRIDE 40   // padded row stride in elems (80B: 16B-aligned, conflict-free)
#define GEMM_SMEM (STAGES * 128 * SSTRIDE * 2 * 2)   // A + B, bf16

__global__ void __launch_bounds__(256) gemm_mma_kernel(
    const __nv_bfloat16* __restrict__ A,
    const __nv_bfloat16* __restrict__ Bm,
    float* __restrict__ C,
    const float* __restrict__ bias) {
    extern __shared__ __align__(16) __nv_bfloat16 sm[];
    __nv_bfloat16* AsP = sm;                                // [STAGES][128][SSTRIDE]
    __nv_bfloat16* BsP = sm + STAGES * 128 * SSTRIDE;

    const int tid = threadIdx.x;
    const int wid = tid >> 5, lane = tid & 31;
    const int wm = wid >> 2, wn = wid & 3;     // warp grid 2 x 4
    const int tn0 = blockIdx.x * 128;
    const int tm0 = blockIdx.y * 128;

    const __nv_bfloat16* Ag = A + (size_t)tm0 * GK;
    const __nv_bfloat16* Bg = Bm + (size_t)tn0 * GK;

    const uint32_t smA = (uint32_t)__cvta_generic_to_shared(AsP);
    const uint32_t smB = (uint32_t)__cvta_generic_to_shared(BsP);

    float acc[4][4][4];
#pragma unroll
    for (int i = 0; i < 4; i++)
#pragma unroll
        for (int j = 0; j < 4; j++)
#pragma unroll
            for (int r = 0; r < 4; r++) acc[i][j][r] = 0.f;

    auto load_stage = [&](int it, int buf) {
        const int k0 = it * BK;
#pragma unroll
        for (int t = 0; t < 4; t++) {
            int ee = tid + t * 256;
            int row = (ee & 511) >> 2;
            int seg = ee & 3;                  // 8-elem (16B) segment
            const __nv_bfloat16* gp;
            uint32_t sp;
            if (ee < 512) {
                gp = Ag + (size_t)row * GK + k0 + seg * 8;
                sp = smA + (uint32_t)(((buf * 128 + row) * SSTRIDE + seg * 8) * 2);
            } else {
                gp = Bg + (size_t)row * GK + k0 + seg * 8;
                sp = smB + (uint32_t)(((buf * 128 + row) * SSTRIDE + seg * 8) * 2);
            }
            asm volatile("cp.async.cg.shared.global [%0], [%1], 16;"
                         :: "r"(sp), "l"(gp));
        }
        asm volatile("cp.async.commit_group;" ::: "memory");
    };

    // prologue: stages 0..3
    load_stage(0, 0); load_stage(1, 1); load_stage(2, 2); load_stage(3, 3);

    for (int it = 0; it < NKIT; it++) {
        const int buf = it % STAGES;
        asm volatile("cp.async.wait_group 3;" ::: "memory");
        __syncthreads();
        // prefetch stage it+4 into buffer of stage it-1 (safe: sync above)
        if (it + 4 < NKIT) {
            load_stage(it + 4, (it + 4) % STAGES);
        } else {
            asm volatile("cp.async.commit_group;" ::: "memory");
        }

#pragma unroll
        for (int ks = 0; ks < 2; ks++) {
            const int kb = ks * 16;
            uint32_t a[4][4], b[4][2];
            const int mat = lane >> 3, r8 = lane & 7;
#pragma unroll
            for (int mt = 0; mt < 4; mt++) {
                int row = wm * 64 + mt * 16 + (mat & 1) * 8 + r8;
                int col = kb + (mat >> 1) * 8;
                uint32_t ad = smA + (uint32_t)(((buf * 128 + row) * SSTRIDE + col) * 2);
                asm volatile(
                    "ldmatrix.sync.aligned.m8n8.x4.shared.b16 {%0,%1,%2,%3}, [%4];"
                    : "=r"(a[mt][0]), "=r"(a[mt][1]), "=r"(a[mt][2]), "=r"(a[mt][3])
                    : "r"(ad));
            }
#pragma unroll
            for (int p = 0; p < 2; p++) {
                int nrow = wn * 32 + p * 16 + (mat >> 1) * 8 + r8;
                int col = kb + (mat & 1) * 8;
                uint32_t bd = smB + (uint32_t)(((buf * 128 + nrow) * SSTRIDE + col) * 2);
                uint32_t q0, q1, q2, q3;
                asm volatile(
                    "ldmatrix.sync.aligned.m8n8.x4.shared.b16 {%0,%1,%2,%3}, [%4];"
                    : "=r"(q0), "=r"(q1), "=r"(q2), "=r"(q3)
                    : "r"(bd));
                b[2 * p][0] = q0; b[2 * p][1] = q1;
                b[2 * p + 1][0] = q2; b[2 * p + 1][1] = q3;
            }
#pragma unroll
            for (int mt = 0; mt < 4; mt++)
#pragma unroll
                for (int nt = 0; nt < 4; nt++) {
                    asm volatile(
                        "mma.sync.aligned.m16n8k16.row.col.f32.bf16.bf16.f32 "
                        "{%0,%1,%2,%3}, {%4,%5,%6,%7}, {%8,%9}, {%0,%1,%2,%3};"
                        : "+f"(acc[mt][nt][0]), "+f"(acc[mt][nt][1]),
                          "+f"(acc[mt][nt][2]), "+f"(acc[mt][nt][3])
                        : "r"(a[mt][0]), "r"(a[mt][1]), "r"(a[mt][2]), "r"(a[mt][3]),
                          "r"(b[nt][0]), "r"(b[nt][1]));
                }
        }
    }

    // epilogue: c0,c1 -> (row, col..col+1); c2,c3 -> (row+8, ...)
    const int rl = lane >> 2, cl = (lane & 3) * 2;
#pragma unroll
    for (int mt = 0; mt < 4; mt++) {
        int row = tm0 + wm * 64 + mt * 16 + rl;
#pragma unroll
        for (int nt = 0; nt < 4; nt++) {
            int col = tn0 + wn * 32 + nt * 8 + cl;
            float b0 = 0.f, b1 = 0.f;
            if (bias) { b0 = bias[col]; b1 = bias[col + 1]; }
            *(float2*)(C + (size_t)row * 1024 + col) =
                make_float2(acc[mt][nt][0] + b0, acc[mt][nt][1] + b1);
            *(float2*)(C + (size_t)(row + 8) * 1024 + col) =
                make_float2(acc[mt][nt][2] + b0, acc[mt][nt][3] + b1);
        }
    }
}

// ---------------------------------------------------------------------------
// Split fp32 -> bf16 hi/lo.  act=1: [hi|hi|lo]   act=0 (weight): [hi|lo|hi]
// ---------------------------------------------------------------------------
__device__ __forceinline__ void split_row(const float* __restrict__ in,
                                          __nv_bfloat16* __restrict__ out,
                                          size_t idx, int act) {
    int row = (int)(idx >> 10);
    int k = (int)(idx & 1023);
    float4 v = *(const float4*)(in + idx);
    __nv_bfloat16 h0 = __float2bfloat16_rn(v.x), h1 = __float2bfloat16_rn(v.y);
    __nv_bfloat16 h2 = __float2bfloat16_rn(v.z), h3 = __float2bfloat16_rn(v.w);
    __nv_bfloat16 l0 = __float2bfloat16_rn(v.x - __bfloat162float(h0));
    __nv_bfloat16 l1 = __float2bfloat16_rn(v.y - __bfloat162float(h1));
    __nv_bfloat16 l2 = __float2bfloat16_rn(v.z - __bfloat162float(h2));
    __nv_bfloat16 l3 = __float2bfloat16_rn(v.w - __bfloat162float(h3));
    __nv_bfloat162 hA = __nv_bfloat162(h0, h1), hB = __nv_bfloat162(h2, h3);
    __nv_bfloat162 lA = __nv_bfloat162(l0, l1), lB = __nv_bfloat162(l2, l3);
    __nv_bfloat162* o0 = (__nv_bfloat162*)(out + (size_t)row * GK + k);
    __nv_bfloat162* o1 = (__nv_bfloat162*)(out + (size_t)row * GK + 1024 + k);
    __nv_bfloat162* o2 = (__nv_bfloat162*)(out + (size_t)row * GK + 2048 + k);
    o0[0] = hA; o0[1] = hB;
    if (act) { o1[0] = hA; o1[1] = hB; o2[0] = lA; o2[1] = lB; }
    else     { o1[0] = lA; o1[1] = lB; o2[0] = hA; o2[1] = hB; }
}

__global__ void __launch_bounds__(256) split_kernel(const float* __restrict__ in,
                                                    __nv_bfloat16* __restrict__ out,
                                                    int act) {
    size_t idx = ((size_t)blockIdx.x * 256 + threadIdx.x) * 4;
    split_row(in, out, idx, act);
}

// fused split: blocks [0,1024)=Wq->Ws0, [1024,2048)=Wo->Ws1, [2048,4096)=X->As
__global__ void __launch_bounds__(256) fused_split_kernel(
    const float* __restrict__ Wq, const float* __restrict__ Wo,
    const float* __restrict__ X,
    __nv_bfloat16* __restrict__ Ws0, __nv_bfloat16* __restrict__ Ws1,
    __nv_bfloat16* __restrict__ As) {
    int b = blockIdx.x;
    if (b < 1024) {
        split_row(Wq, Ws0, ((size_t)b * 256 + threadIdx.x) * 4, 0);
    } else if (b < 2048) {
        split_row(Wo, Ws1, ((size_t)(b - 1024) * 256 + threadIdx.x) * 4, 0);
    } else {
        split_row(X, As, ((size_t)(b - 2048) * 256 + threadIdx.x) * 4, 1);
    }
}

// ---------------------------------------------------------------------------
// c[m] = sum(keys[m]) / (sqrt(D) * ||keys[m]||)
// ---------------------------------------------------------------------------
__global__ void __launch_bounds__(256) compute_c_kernel(const float* __restrict__ keys) {
    int warp = threadIdx.x >> 5;
    int lane = threadIdx.x & 31;
    int row  = blockIdx.x * 8 + warp;
    const float4* kp = reinterpret_cast<const float4*>(keys + (size_t)row * DDIM);
    float s = 0.f, ss = 0.f;
#pragma unroll
    for (int i = 0; i < 8; i++) {
        float4 v = kp[lane + i * 32];
        s  += (v.x + v.y) + (v.z + v.w);
        ss += v.x * v.x + v.y * v.y + v.z * v.z + v.w * v.w;
    }
#pragma unroll
    for (int o = 16; o > 0; o >>= 1) {
        s  += __shfl_xor_sync(0xffffffffu, s, o);
        ss += __shfl_xor_sync(0xffffffffu, ss, o);
    }
    if (lane == 0) g_c[row] = s / (32.0f * sqrtf(ss));
}

// ---------------------------------------------------------------------------
// top-32 (desc, block 0) / bottom-32 (asc, block 1); jax.top_k tie semantics
// ---------------------------------------------------------------------------
__global__ void __launch_bounds__(1024) select_kernel() {
    __shared__ float swv[32];
    __shared__ int   swi[32];
    __shared__ int   s_wi;
    const int tid  = threadIdx.x;
    const int lane = tid & 31, warp = tid >> 5;
    const int phase = blockIdx.x;

    float v[32];
#pragma unroll
    for (int k = 0; k < 32; k++) v[k] = g_c[k * 1024 + tid];

    float bv = v[0]; int bk = 0;
#pragma unroll
    for (int k = 1; k < 32; k++) {
        bool b = (phase == 0) ? (v[k] > bv) : (v[k] < bv);
        if (b) { bv = v[k]; bk = k; }
    }

    for (int r = 0; r < KSEL; r++) {
        float cv = bv; int ci = bk * 1024 + tid;
#pragma unroll
        for (int o = 16; o > 0; o >>= 1) {
            float ov = __shfl_xor_sync(0xffffffffu, cv, o);
            int   oi = __shfl_xor_sync(0xffffffffu, ci, o);
            bool b = (phase == 0) ? ((ov > cv) || (ov == cv && oi < ci))
                                  : ((ov < cv) || (ov == cv && oi < ci));
            if (b) { cv = ov; ci = oi; }
        }
        if (lane == 0) { swv[warp] = cv; swi[warp] = ci; }
        __syncthreads();
        if (warp == 0) {
            cv = swv[lane]; ci = swi[lane];
#pragma unroll
            for (int o = 16; o > 0; o >>= 1) {
                float ov = __shfl_xor_sync(0xffffffffu, cv, o);
                int   oi = __shfl_xor_sync(0xffffffffu, ci, o);
                bool b = (phase == 0) ? ((ov > cv) || (ov == cv && oi < ci))
                                      : ((ov < cv) || (ov == cv && oi < ci));
                if (b) { cv = ov; ci = oi; }
            }
            if (lane == 0) { s_wi = ci; g_sel[phase][r] = ci; }
        }
        __syncthreads();
        int wi = s_wi;
        if ((wi & 1023) == tid) {
            int wk = wi >> 10;
#pragma unroll
            for (int k = 0; k < 32; k++)
                if (k == wk) v[k] = (phase == 0) ? -INFINITY : INFINITY;
            bv = v[0]; bk = 0;
#pragma unroll
            for (int k = 1; k < 32; k++) {
                bool b = (phase == 0) ? (v[k] > bv) : (v[k] < bv);
                if (b) { bv = v[k]; bk = k; }
            }
        }
        __syncthreads();
    }
}

// ---------------------------------------------------------------------------
// wbar partials: g_wpart[by][col] = sum over 128 rows (chunk by) of Wq[o][col]
// ---------------------------------------------------------------------------
__global__ void __launch_bounds__(128) wbar_kernel(const float* __restrict__ Wq) {
    int col = blockIdx.x * 128 + threadIdx.x;
    int o0 = blockIdx.y * 128;
    float s = 0.f;
#pragma unroll 8
    for (int o = 0; o < 128; o++)
        s += Wq[(size_t)(o0 + o) * DDIM + col];
    g_wpart[blockIdx.y][col] = s;
}

// ---------------------------------------------------------------------------
// sign(qm):  qm[row] = X[row] . wbar   (wbar = colmean of Wq)
// grid 256 blocks x 256 thr; block handles 8 rows (one per warp)
// ---------------------------------------------------------------------------
__global__ void __launch_bounds__(256) qm_sign_kernel(const float* __restrict__ X) {
    __shared__ float wb[DDIM];
    const int tid = threadIdx.x;
    for (int c = tid; c < DDIM; c += 256) {
        float s = 0.f;
#pragma unroll
        for (int by = 0; by < 8; by++) s += g_wpart[by][c];
        wb[c] = s;
    }
    __syncthreads();
    const int lane = tid & 31, w = tid >> 5;
    int row = blockIdx.x * 8 + w;
    const float4* xp = reinterpret_cast<const float4*>(X + (size_t)row * DDIM);
    const float4* wp = reinterpret_cast<const float4*>(wb);
    float s = 0.f;
#pragma unroll
    for (int i = 0; i < 8; i++) {
        float4 a = xp[lane + i * 32];
        float4 b = wp[lane + i * 32];
        s += a.x * b.x + a.y * b.y + a.z * b.z + a.w * b.w;
    }
#pragma unroll
    for (int o = 16; o > 0; o >>= 1) s += __shfl_xor_sync(0xffffffffu, s, o);
    if (lane == 0) g_sign[row] = (s >= 0.f) ? 0 : 1;
}

// ---------------------------------------------------------------------------
// K/V projections for the two candidate selections.
// grid (16 coltiles of 64, 2 sel, 2 mat); block computes 32 slots x 64 cols.
// ---------------------------------------------------------------------------
__global__ void __launch_bounds__(256) kvproj_kernel(const float* __restrict__ keys,
                                                     const float* __restrict__ vals,
                                                     const float* __restrict__ Wk,
                                                     const float* __restrict__ Wv) {
    __shared__ float As[32][64];
    __shared__ float Bs[64][68];
    __shared__ int sidx[32];
    const int tid = threadIdx.x;
    const int col0 = blockIdx.x * 64;
    const int sel = blockIdx.y;
    const int mat = blockIdx.z;
    const float* src = mat ? vals : keys;
    const float* W   = mat ? Wv : Wk;
    float* dst = mat ? &g_vproj[sel][0][0] : &g_kproj[sel][0][0];
    if (tid < 32) sidx[tid] = g_sel[sel][tid];
    __syncthreads();
    const int tx = tid & 7, ty = tid >> 3;   // ty = slot (0..31), tx -> 8 cols
    float acc[8] = {};
    for (int kk = 0; kk < DDIM; kk += 64) {
#pragma unroll
        for (int t = 0; t < 2; t++) {
            int e = tid + t * 256;
            int slot = e >> 4, f4 = e & 15;
            *reinterpret_cast<float4*>(&As[slot][f4 * 4]) =
                *reinterpret_cast<const float4*>(&src[(size_t)sidx[slot] * DDIM + kk + f4 * 4]);
        }
#pragma unroll
        for (int t = 0; t < 4; t++) {
            int e = tid + t * 256;
            int col = e >> 4, f4 = e & 15;
            float4 v = *reinterpret_cast<const float4*>(&W[(size_t)(col0 + col) * DDIM + kk + f4 * 4]);
            Bs[f4 * 4 + 0][col] = v.x; Bs[f4 * 4 + 1][col] = v.y;
            Bs[f4 * 4 + 2][col] = v.z; Bs[f4 * 4 + 3][col] = v.w;
        }
        __syncthreads();
#pragma unroll
        for (int k = 0; k < 64; k++) {
            float a = As[ty][k];
#pragma unroll
            for (int j = 0; j < 8; j++)
                acc[j] = fmaf(a, Bs[k][tx * 8 + j], acc[j]);
        }
        __syncthreads();
    }
#pragma unroll
    for (int j = 0; j < 8; j += 4)
        *reinterpret_cast<float4*>(&dst[(size_t)ty * DDIM + col0 + tx * 8 + j]) =
            make_float4(acc[j], acc[j + 1], acc[j + 2], acc[j + 3]);
}

// ---------------------------------------------------------------------------
// attention. 16 positions/block, loop over heads.
// ---------------------------------------------------------------------------
__global__ void __launch_bounds__(256) attn_kernel(float* __restrict__ out_attn,
                                                   float* __restrict__ out_selidx) {
    __shared__ float qs[16][68];
    __shared__ float Kh[32][65];
    __shared__ float Vh[32][65];
    __shared__ float sc[16][33];
    __shared__ float aacc[16][32];
    __shared__ int ssel[16];
    const int tid = threadIdx.x;
    const int p0 = blockIdx.x * 16;
    if (tid < 16) ssel[tid] = g_sign[p0 + tid];
#pragma unroll
    for (int t = 0; t < 2; t++) {
        int i = tid + t * 256;
        aacc[i >> 5][i & 31] = 0.f;
    }
    __syncthreads();
    int use0 = 0, use1 = 0;
#pragma unroll
    for (int p = 0; p < 16; p++) { if (ssel[p]) use1++; else use0++; }

    for (int h = 0; h < 16; h++) {
        {
            int pos = tid >> 4, f4 = tid & 15;
            float4 v = *reinterpret_cast<const float4*>(&g_q[(size_t)(p0 + pos) * DDIM + h * 64 + f4 * 4]);
            qs[pos][f4 * 4 + 0] = v.x; qs[pos][f4 * 4 + 1] = v.y;
            qs[pos][f4 * 4 + 2] = v.z; qs[pos][f4 * 4 + 3] = v.w;
        }
        for (int sel = 0; sel < 2; sel++) {
            if (sel == 0 ? (use0 == 0) : (use1 == 0)) continue;
#pragma unroll
            for (int t = 0; t < 2; t++) {
                int e = tid + t * 256;
                int slot = e >> 4, f4 = e & 15;
                float4 kv = *reinterpret_cast<const float4*>(&g_kproj[sel][slot][h * 64 + f4 * 4]);
                Kh[slot][f4 * 4 + 0] = kv.x; Kh[slot][f4 * 4 + 1] = kv.y;
                Kh[slot][f4 * 4 + 2] = kv.z; Kh[slot][f4 * 4 + 3] = kv.w;
                float4 vv = *reinterpret_cast<const float4*>(&g_vproj[sel][slot][h * 64 + f4 * 4]);
                Vh[slot][f4 * 4 + 0] = vv.x; Vh[slot][f4 * 4 + 1] = vv.y;
                Vh[slot][f4 * 4 + 2] = vv.z; Vh[slot][f4 * 4 + 3] = vv.w;
            }
            __syncthreads();
#pragma unroll
            for (int t = 0; t < 2; t++) {
                int idx = tid + t * 256;
                int pos = idx >> 5, slot = idx & 31;
                if (ssel[pos] == sel) {
                    float s = 0.f;
#pragma unroll
                    for (int k = 0; k < 64; k++) s = fmaf(qs[pos][k], Kh[slot][k], s);
                    sc[pos][slot] = s * 0.125f;
                }
            }
            __syncthreads();
            {
                int w = tid >> 5, lane = tid & 31;
#pragma unroll
                for (int t = 0; t < 2; t++) {
                    int pos = w + t * 8;
                    if (ssel[pos] == sel) {
                        float vsc = sc[pos][lane];
                        float mx = vsc;
#pragma unroll
                        for (int o = 16; o > 0; o >>= 1)
                            mx = fmaxf(mx, __shfl_xor_sync(0xffffffffu, mx, o));
                        float e = expf(vsc - mx);
                        float sm = e;
#pragma unroll
                        for (int o = 16; o > 0; o >>= 1)
                            sm += __shfl_xor_sync(0xffffffffu, sm, o);
                        float a = e / sm;
                        sc[pos][lane] = a;
                        aacc[pos][lane] += a * 0.0625f;
                    }
                }
            }
            __syncthreads();
#pragma unroll
            for (int t = 0; t < 4; t++) {
                int idx = tid + t * 256;
                int pos = idx >> 6, e = idx & 63;
                if (ssel[pos] == sel) {
                    float s = 0.f;
#pragma unroll
                    for (int slot = 0; slot < 32; slot++)
                        s = fmaf(sc[pos][slot], Vh[slot][e], s);
                    g_ctx[(size_t)(p0 + pos) * DDIM + h * 64 + e] = s;
                }
            }
            __syncthreads();
        }
    }
#pragma unroll
    for (int t = 0; t < 2; t++) {
        int idx = tid + t * 256;
        int pos = idx >> 5, slot = idx & 31;
        if (out_attn)
            out_attn[(size_t)(p0 + pos) * KSEL + slot] = aacc[pos][slot];
        if (out_selidx)
            out_selidx[(size_t)(p0 + pos) * KSEL + slot] = (float)g_sel[ssel[pos]][slot];
    }
}

// ---------------------------------------------------------------------------
// LayerNorm in-place
// ---------------------------------------------------------------------------
__global__ void __launch_bounds__(256) ln_kernel(float* __restrict__ io,
                                                 const float* __restrict__ gamma,
                                                 const float* __restrict__ beta) {
    int row = blockIdx.x;
    float4* p = reinterpret_cast<float4*>(io + (size_t)row * DDIM);
    float4 v = p[threadIdx.x];
    float s  = (v.x + v.y) + (v.z + v.w);
    float ss = v.x * v.x + v.y * v.y + v.z * v.z + v.w * v.w;
    __shared__ float r1[8], r2[8];
    __shared__ float fmu, frs;
    int lane = threadIdx.x & 31, w = threadIdx.x >> 5;
#pragma unroll
    for (int o = 16; o > 0; o >>= 1) {
        s  += __shfl_xor_sync(0xffffffffu, s, o);
        ss += __shfl_xor_sync(0xffffffffu, ss, o);
    }
    if (lane == 0) { r1[w] = s; r2[w] = ss; }
    __syncthreads();
    if (threadIdx.x == 0) {
        float ts = 0.f, tss = 0.f;
#pragma unroll
        for (int i = 0; i < 8; i++) { ts += r1[i]; tss += r2[i]; }
        float mu  = ts * (1.f / 1024.f);
        float var = tss * (1.f / 1024.f) - mu * mu;
        fmu = mu;
        frs = rsqrtf(var + 1e-5f);
    }
    __syncthreads();
    float mu = fmu, rstd = frs;
    const float4 g = reinterpret_cast<const float4*>(gamma)[threadIdx.x];
    const float4 b = reinterpret_cast<const float4*>(beta)[threadIdx.x];
    v.x = (v.x - mu) * rstd * g.x + b.x;
    v.y = (v.y - mu) * rstd * g.y + b.y;
    v.z = (v.z - mu) * rstd * g.z + b.z;
    v.w = (v.w - mu) * rstd * g.w + b.w;
    p[threadIdx.x] = v;
}

// ---------------------------------------------------------------------------
extern "C" void kernel_launch(void* const* d_in, const int* in_sizes, int n_in,
                              void* d_out, int out_size) {
    const float* X     = (const float*)d_in[0];
    const float* keys  = (const float*)d_in[1];
    const float* vals  = (const float*)d_in[2];
    const float* Wq    = (const float*)d_in[3];
    const float* Wk    = (const float*)d_in[4];
    const float* Wv    = (const float*)d_in[5];
    const float* Wo    = (const float*)d_in[6];
    const float* bo    = (const float*)d_in[7];
    const float* gamma = (const float*)d_in[8];
    const float* beta  = (const float*)d_in[9];

    float* out = (float*)d_out;
    float* out_attn = nullptr;
    float* out_sel  = nullptr;
    const long long base = (long long)BN_POS * DDIM;
    if ((long long)out_size >= base + (long long)BN_POS * KSEL)
        out_attn = out + base;
    if ((long long)out_size >= base + 2LL * BN_POS * KSEL)
        out_sel = out + base + (long long)BN_POS * KSEL;

    void *pq = nullptr, *pctx = nullptr, *pAs = nullptr, *pWs = nullptr;
    cudaGetSymbolAddress(&pq, g_q);
    cudaGetSymbolAddress(&pctx, g_ctx);
    cudaGetSymbolAddress(&pAs, g_As);
    cudaGetSymbolAddress(&pWs, g_Ws);
    __nv_bfloat16* As = (__nv_bfloat16*)pAs;
    __nv_bfloat16* Ws0 = (__nv_bfloat16*)pWs;
    __nv_bfloat16* Ws1 = Ws0 + (size_t)DDIM * GK;

    cudaFuncSetAttribute(gemm_mma_kernel,
                         cudaFuncAttributeMaxDynamicSharedMemorySize, GEMM_SMEM);

    // 1. memory-key statistics + candidate top-k sets (2 parallel blocks)
    compute_c_kernel<<<MDIM / 8, 256>>>(keys);
    select_kernel<<<2, 1024>>>();
    // 2. all splits in one launch
    fused_split_kernel<<<4096, 256>>>(Wq, Wo, X, Ws0, Ws1, As);
    // 3. sign(qm) via wbar GEMV (independent of q-proj)
    wbar_kernel<<<dim3(8, 8), 128>>>(Wq);
    qm_sign_kernel<<<BN_POS / 8, 256>>>(X);
    // 4. q projection (HMMA, 5-stage pipeline)
    gemm_mma_kernel<<<dim3(8, 16), 256, GEMM_SMEM>>>(As, Ws0, (float*)pq, nullptr);
    // 5. K/V projections of the two selections
    kvproj_kernel<<<dim3(16, 2, 2), 256>>>(keys, vals, Wk, Wv);
    // 6. attention
    attn_kernel<<<BN_POS / 16, 256>>>(out_attn, out_sel);
    // 7. split ctx, output projection (HMMA) + bias
    split_kernel<<<(BN_POS * DDIM) / 1024, 256>>>((const float*)pctx, As, 1);
    gemm_mma_kernel<<<dim3(8, 16), 256, GEMM_SMEM>>>(As, Ws1, out, bo);
    // 8. layernorm
    ln_kernel<<<BN_POS, 256>>>(out, gamma, beta);
}

// round 6
// speedup vs baseline: 1.9492x; 1.3465x over previous
#include <cuda_runtime.h>
#include <cuda_bf16.h>
#include <math.h>
#include <cstdint>

// Problem constants
#define BN_POS 2048      // B*N = 4*512
#define MDIM   32768
#define DDIM   1024
#define KSEL   32
#define NHEAD  16
#define GK     3072      // bf16 3-term split: A=[hi|hi|lo], B=[hi|lo|hi]
#define BK     32
#define NKIT   (GK / BK) // 96
#define STAGES 5

// Scratch (device globals; no allocation allowed)
__device__ float g_c[MDIM];
__device__ int   g_sel[2][KSEL];
__device__ float g_kproj[2][KSEL][DDIM];
__device__ float g_vproj[2][KSEL][DDIM];
__device__ float g_q[(size_t)BN_POS * DDIM];
__device__ int   g_sign[BN_POS];
__device__ float g_ctx[(size_t)BN_POS * DDIM];
__device__ float g_p[(size_t)BN_POS * NHEAD * KSEL];   // softmax probs
__device__ float g_wpart[32][DDIM];
__device__ __nv_bfloat16 g_As[(size_t)BN_POS * GK];   // split activations
__device__ __nv_bfloat16 g_Ws[2][(size_t)DDIM * GK];  // split Wq, Wo

// ---------------------------------------------------------------------------
// bf16-split GEMM via mma.sync (HMMA) + ldmatrix + cp.async pipeline.
// C[m][n] = sum_k A[m][k]*B[n][k] (+bias[n]).  M=2048, N=1024, K=GK.
// CTA 128x128, 8 warps (2x4), warp tile 64x32.
// ---------------------------------------------------------------------------
#define SSTRIDE 40   // padded row stride in elems (80B: 16B-aligned, conflict-free)
#define GEMM_SMEM (STAGES * 128 * SSTRIDE * 2 * 2)   // A + B, bf16

__global__ void __launch_bounds__(256) gemm_mma_kernel(
    const __nv_bfloat16* __restrict__ A,
    const __nv_bfloat16* __restrict__ Bm,
    float* __restrict__ C,
    const float* __restrict__ bias) {
    extern __shared__ __align__(16) __nv_bfloat16 sm[];
    __nv_bfloat16* AsP = sm;                                // [STAGES][128][SSTRIDE]
    __nv_bfloat16* BsP = sm + STAGES * 128 * SSTRIDE;

    const int tid = threadIdx.x;
    const int wid = tid >> 5, lane = tid & 31;
    const int wm = wid >> 2, wn = wid & 3;     // warp grid 2 x 4
    const int tn0 = blockIdx.x * 128;
    const int tm0 = blockIdx.y * 128;

    const __nv_bfloat16* Ag = A + (size_t)tm0 * GK;
    const __nv_bfloat16* Bg = Bm + (size_t)tn0 * GK;

    const uint32_t smA = (uint32_t)__cvta_generic_to_shared(AsP);
    const uint32_t smB = (uint32_t)__cvta_generic_to_shared(BsP);

    float acc[4][4][4];
#pragma unroll
    for (int i = 0; i < 4; i++)
#pragma unroll
        for (int j = 0; j < 4; j++)
#pragma unroll
            for (int r = 0; r < 4; r++) acc[i][j][r] = 0.f;

    auto load_stage = [&](int it, int buf) {
        const int k0 = it * BK;
#pragma unroll
        for (int t = 0; t < 4; t++) {
            int ee = tid + t * 256;
            int row = (ee & 511) >> 2;
            int seg = ee & 3;                  // 8-elem (16B) segment
            const __nv_bfloat16* gp;
            uint32_t sp;
            if (ee < 512) {
                gp = Ag + (size_t)row * GK + k0 + seg * 8;
                sp = smA + (uint32_t)(((buf * 128 + row) * SSTRIDE + seg * 8) * 2);
            } else {
                gp = Bg + (size_t)row * GK + k0 + seg * 8;
                sp = smB + (uint32_t)(((buf * 128 + row) * SSTRIDE + seg * 8) * 2);
            }
            asm volatile("cp.async.cg.shared.global [%0], [%1], 16;"
                         :: "r"(sp), "l"(gp));
        }
        asm volatile("cp.async.commit_group;" ::: "memory");
    };

    load_stage(0, 0); load_stage(1, 1); load_stage(2, 2); load_stage(3, 3);

    for (int it = 0; it < NKIT; it++) {
        const int buf = it % STAGES;
        asm volatile("cp.async.wait_group 3;" ::: "memory");
        __syncthreads();
        if (it + 4 < NKIT) {
            load_stage(it + 4, (it + 4) % STAGES);
        } else {
            asm volatile("cp.async.commit_group;" ::: "memory");
        }

#pragma unroll
        for (int ks = 0; ks < 2; ks++) {
            const int kb = ks * 16;
            uint32_t a[4][4], b[4][2];
            const int mat = lane >> 3, r8 = lane & 7;
#pragma unroll
            for (int mt = 0; mt < 4; mt++) {
                int row = wm * 64 + mt * 16 + (mat & 1) * 8 + r8;
                int col = kb + (mat >> 1) * 8;
                uint32_t ad = smA + (uint32_t)(((buf * 128 + row) * SSTRIDE + col) * 2);
                asm volatile(
                    "ldmatrix.sync.aligned.m8n8.x4.shared.b16 {%0,%1,%2,%3}, [%4];"
                    : "=r"(a[mt][0]), "=r"(a[mt][1]), "=r"(a[mt][2]), "=r"(a[mt][3])
                    : "r"(ad));
            }
#pragma unroll
            for (int p = 0; p < 2; p++) {
                int nrow = wn * 32 + p * 16 + (mat >> 1) * 8 + r8;
                int col = kb + (mat & 1) * 8;
                uint32_t bd = smB + (uint32_t)(((buf * 128 + nrow) * SSTRIDE + col) * 2);
                uint32_t q0, q1, q2, q3;
                asm volatile(
                    "ldmatrix.sync.aligned.m8n8.x4.shared.b16 {%0,%1,%2,%3}, [%4];"
                    : "=r"(q0), "=r"(q1), "=r"(q2), "=r"(q3)
                    : "r"(bd));
                b[2 * p][0] = q0; b[2 * p][1] = q1;
                b[2 * p + 1][0] = q2; b[2 * p + 1][1] = q3;
            }
#pragma unroll
            for (int mt = 0; mt < 4; mt++)
#pragma unroll
                for (int nt = 0; nt < 4; nt++) {
                    asm volatile(
                        "mma.sync.aligned.m16n8k16.row.col.f32.bf16.bf16.f32 "
                        "{%0,%1,%2,%3}, {%4,%5,%6,%7}, {%8,%9}, {%0,%1,%2,%3};"
                        : "+f"(acc[mt][nt][0]), "+f"(acc[mt][nt][1]),
                          "+f"(acc[mt][nt][2]), "+f"(acc[mt][nt][3])
                        : "r"(a[mt][0]), "r"(a[mt][1]), "r"(a[mt][2]), "r"(a[mt][3]),
                          "r"(b[nt][0]), "r"(b[nt][1]));
                }
        }
    }

    const int rl = lane >> 2, cl = (lane & 3) * 2;
#pragma unroll
    for (int mt = 0; mt < 4; mt++) {
        int row = tm0 + wm * 64 + mt * 16 + rl;
#pragma unroll
        for (int nt = 0; nt < 4; nt++) {
            int col = tn0 + wn * 32 + nt * 8 + cl;
            float b0 = 0.f, b1 = 0.f;
            if (bias) { b0 = bias[col]; b1 = bias[col + 1]; }
            *(float2*)(C + (size_t)row * 1024 + col) =
                make_float2(acc[mt][nt][0] + b0, acc[mt][nt][1] + b1);
            *(float2*)(C + (size_t)(row + 8) * 1024 + col) =
                make_float2(acc[mt][nt][2] + b0, acc[mt][nt][3] + b1);
        }
    }
}

// ---------------------------------------------------------------------------
// Split fp32 -> bf16 hi/lo.  act=1: [hi|hi|lo]   act=0 (weight): [hi|lo|hi]
// ---------------------------------------------------------------------------
__device__ __forceinline__ void split_row(const float* __restrict__ in,
                                          __nv_bfloat16* __restrict__ out,
                                          size_t idx, int act) {
    int row = (int)(idx >> 10);
    int k = (int)(idx & 1023);
    float4 v = *(const float4*)(in + idx);
    __nv_bfloat16 h0 = __float2bfloat16_rn(v.x), h1 = __float2bfloat16_rn(v.y);
    __nv_bfloat16 h2 = __float2bfloat16_rn(v.z), h3 = __float2bfloat16_rn(v.w);
    __nv_bfloat16 l0 = __float2bfloat16_rn(v.x - __bfloat162float(h0));
    __nv_bfloat16 l1 = __float2bfloat16_rn(v.y - __bfloat162float(h1));
    __nv_bfloat16 l2 = __float2bfloat16_rn(v.z - __bfloat162float(h2));
    __nv_bfloat16 l3 = __float2bfloat16_rn(v.w - __bfloat162float(h3));
    __nv_bfloat162 hA = __nv_bfloat162(h0, h1), hB = __nv_bfloat162(h2, h3);
    __nv_bfloat162 lA = __nv_bfloat162(l0, l1), lB = __nv_bfloat162(l2, l3);
    __nv_bfloat162* o0 = (__nv_bfloat162*)(out + (size_t)row * GK + k);
    __nv_bfloat162* o1 = (__nv_bfloat162*)(out + (size_t)row * GK + 1024 + k);
    __nv_bfloat162* o2 = (__nv_bfloat162*)(out + (size_t)row * GK + 2048 + k);
    o0[0] = hA; o0[1] = hB;
    if (act) { o1[0] = hA; o1[1] = hB; o2[0] = lA; o2[1] = lB; }
    else     { o1[0] = lA; o1[1] = lB; o2[0] = hA; o2[1] = hB; }
}

__global__ void __launch_bounds__(256) split_kernel(const float* __restrict__ in,
                                                    __nv_bfloat16* __restrict__ out,
                                                    int act) {
    split_row(in, out, ((size_t)blockIdx.x * 256 + threadIdx.x) * 4, act);
}

// blocks [0,1024)=Wq->Ws0, [1024,2048)=Wo->Ws1, [2048,4096)=X->As
__global__ void __launch_bounds__(256) fused_split_kernel(
    const float* __restrict__ Wq, const float* __restrict__ Wo,
    const float* __restrict__ X,
    __nv_bfloat16* __restrict__ Ws0, __nv_bfloat16* __restrict__ Ws1,
    __nv_bfloat16* __restrict__ As) {
    int b = blockIdx.x;
    if (b < 1024) {
        split_row(Wq, Ws0, ((size_t)b * 256 + threadIdx.x) * 4, 0);
    } else if (b < 2048) {
        split_row(Wo, Ws1, ((size_t)(b - 1024) * 256 + threadIdx.x) * 4, 0);
    } else {
        split_row(X, As, ((size_t)(b - 2048) * 256 + threadIdx.x) * 4, 1);
    }
}

// ---------------------------------------------------------------------------
// c[m] = sum(keys[m]) / (sqrt(D) * ||keys[m]||)
// ---------------------------------------------------------------------------
__global__ void __launch_bounds__(256) compute_c_kernel(const float* __restrict__ keys) {
    int warp = threadIdx.x >> 5;
    int lane = threadIdx.x & 31;
    int row  = blockIdx.x * 8 + warp;
    const float4* kp = reinterpret_cast<const float4*>(keys + (size_t)row * DDIM);
    float s = 0.f, ss = 0.f;
#pragma unroll
    for (int i = 0; i < 8; i++) {
        float4 v = kp[lane + i * 32];
        s  += (v.x + v.y) + (v.z + v.w);
        ss += v.x * v.x + v.y * v.y + v.z * v.z + v.w * v.w;
    }
#pragma unroll
    for (int o = 16; o > 0; o >>= 1) {
        s  += __shfl_xor_sync(0xffffffffu, s, o);
        ss += __shfl_xor_sync(0xffffffffu, ss, o);
    }
    if (lane == 0) g_c[row] = s / (32.0f * sqrtf(ss));
}

// ---------------------------------------------------------------------------
// top-32 (desc, block 0) / bottom-32 (asc, block 1); jax.top_k tie semantics
// ---------------------------------------------------------------------------
__global__ void __launch_bounds__(1024) select_kernel() {
    __shared__ float swv[32];
    __shared__ int   swi[32];
    __shared__ int   s_wi;
    const int tid  = threadIdx.x;
    const int lane = tid & 31, warp = tid >> 5;
    const int phase = blockIdx.x;

    float v[32];
#pragma unroll
    for (int k = 0; k < 32; k++) v[k] = g_c[k * 1024 + tid];

    float bv = v[0]; int bk = 0;
#pragma unroll
    for (int k = 1; k < 32; k++) {
        bool b = (phase == 0) ? (v[k] > bv) : (v[k] < bv);
        if (b) { bv = v[k]; bk = k; }
    }

    for (int r = 0; r < KSEL; r++) {
        float cv = bv; int ci = bk * 1024 + tid;
#pragma unroll
        for (int o = 16; o > 0; o >>= 1) {
            float ov = __shfl_xor_sync(0xffffffffu, cv, o);
            int   oi = __shfl_xor_sync(0xffffffffu, ci, o);
            bool b = (phase == 0) ? ((ov > cv) || (ov == cv && oi < ci))
                                  : ((ov < cv) || (ov == cv && oi < ci));
            if (b) { cv = ov; ci = oi; }
        }
        if (lane == 0) { swv[warp] = cv; swi[warp] = ci; }
        __syncthreads();
        if (warp == 0) {
            cv = swv[lane]; ci = swi[lane];
#pragma unroll
            for (int o = 16; o > 0; o >>= 1) {
                float ov = __shfl_xor_sync(0xffffffffu, cv, o);
                int   oi = __shfl_xor_sync(0xffffffffu, ci, o);
                bool b = (phase == 0) ? ((ov > cv) || (ov == cv && oi < ci))
                                      : ((ov < cv) || (ov == cv && oi < ci));
                if (b) { cv = ov; ci = oi; }
            }
            if (lane == 0) { s_wi = ci; g_sel[phase][r] = ci; }
        }
        __syncthreads();
        int wi = s_wi;
        if ((wi & 1023) == tid) {
            int wk = wi >> 10;
#pragma unroll
            for (int k = 0; k < 32; k++)
                if (k == wk) v[k] = (phase == 0) ? -INFINITY : INFINITY;
            bv = v[0]; bk = 0;
#pragma unroll
            for (int k = 1; k < 32; k++) {
                bool b = (phase == 0) ? (v[k] > bv) : (v[k] < bv);
                if (b) { bv = v[k]; bk = k; }
            }
        }
        __syncthreads();
    }
}

// ---------------------------------------------------------------------------
// wbar partials: g_wpart[ry][col] = sum over 32 rows (chunk ry) of Wq[o][col]
// ---------------------------------------------------------------------------
__global__ void __launch_bounds__(128) wbar_kernel(const float* __restrict__ Wq) {
    int col = blockIdx.x * 128 + threadIdx.x;
    int o0 = blockIdx.y * 32;
    float s = 0.f;
#pragma unroll 8
    for (int o = 0; o < 32; o++)
        s += Wq[(size_t)(o0 + o) * DDIM + col];
    g_wpart[blockIdx.y][col] = s;
}

// ---------------------------------------------------------------------------
// sign(qm):  qm[row] = X[row] . wbar
// ---------------------------------------------------------------------------
__global__ void __launch_bounds__(256) qm_sign_kernel(const float* __restrict__ X) {
    __shared__ float wb[DDIM];
    const int tid = threadIdx.x;
    for (int c = tid; c < DDIM; c += 256) {
        float s = 0.f;
#pragma unroll
        for (int by = 0; by < 32; by++) s += g_wpart[by][c];
        wb[c] = s;
    }
    __syncthreads();
    const int lane = tid & 31, w = tid >> 5;
    int row = blockIdx.x * 8 + w;
    const float4* xp = reinterpret_cast<const float4*>(X + (size_t)row * DDIM);
    const float4* wp = reinterpret_cast<const float4*>(wb);
    float s = 0.f;
#pragma unroll
    for (int i = 0; i < 8; i++) {
        float4 a = xp[lane + i * 32];
        float4 b = wp[lane + i * 32];
        s += a.x * b.x + a.y * b.y + a.z * b.z + a.w * b.w;
    }
#pragma unroll
    for (int o = 16; o > 0; o >>= 1) s += __shfl_xor_sync(0xffffffffu, s, o);
    if (lane == 0) g_sign[row] = (s >= 0.f) ? 0 : 1;
}

// ---------------------------------------------------------------------------
// K/V projections for the two candidate selections (fp32, exact).
// grid (16 coltiles of 64, 2 sel, 2 mat)
// ---------------------------------------------------------------------------
__global__ void __launch_bounds__(256) kvproj_kernel(const float* __restrict__ keys,
                                                     const float* __restrict__ vals,
                                                     const float* __restrict__ Wk,
                                                     const float* __restrict__ Wv) {
    __shared__ float As[32][64];
    __shared__ float Bs[64][68];
    __shared__ int sidx[32];
    const int tid = threadIdx.x;
    const int col0 = blockIdx.x * 64;
    const int sel = blockIdx.y;
    const int mat = blockIdx.z;
    const float* src = mat ? vals : keys;
    const float* W   = mat ? Wv : Wk;
    float* dst = mat ? &g_vproj[sel][0][0] : &g_kproj[sel][0][0];
    if (tid < 32) sidx[tid] = g_sel[sel][tid];
    __syncthreads();
    const int tx = tid & 7, ty = tid >> 3;   // ty = slot (0..31), tx -> 8 cols
    float acc[8] = {};
    for (int kk = 0; kk < DDIM; kk += 64) {
#pragma unroll
        for (int t = 0; t < 2; t++) {
            int e = tid + t * 256;
            int slot = e >> 4, f4 = e & 15;
            *reinterpret_cast<float4*>(&As[slot][f4 * 4]) =
                *reinterpret_cast<const float4*>(&src[(size_t)sidx[slot] * DDIM + kk + f4 * 4]);
        }
#pragma unroll
        for (int t = 0; t < 4; t++) {
            int e = tid + t * 256;
            int col = e >> 4, f4 = e & 15;
            float4 v = *reinterpret_cast<const float4*>(&W[(size_t)(col0 + col) * DDIM + kk + f4 * 4]);
            Bs[f4 * 4 + 0][col] = v.x; Bs[f4 * 4 + 1][col] = v.y;
            Bs[f4 * 4 + 2][col] = v.z; Bs[f4 * 4 + 3][col] = v.w;
        }
        __syncthreads();
#pragma unroll
        for (int k = 0; k < 64; k++) {
            float a = As[ty][k];
#pragma unroll
            for (int j = 0; j < 8; j++)
                acc[j] = fmaf(a, Bs[k][tx * 8 + j], acc[j]);
        }
        __syncthreads();
    }
#pragma unroll
    for (int j = 0; j < 8; j += 4)
        *reinterpret_cast<float4*>(&dst[(size_t)ty * DDIM + col0 + tx * 8 + j]) =
            make_float4(acc[j], acc[j + 1], acc[j + 2], acc[j + 3]);
}

// ---------------------------------------------------------------------------
// scores+softmax: grid (64 posblocks of 32, 16 heads), block 256 (8 warps).
// warp handles 4 positions; lane = slot. probs -> g_p[pos][h][slot].
// ---------------------------------------------------------------------------
__global__ void __launch_bounds__(256) scores_kernel() {
    __shared__ float Ks[2][32][65];
    __shared__ float qs[32][65];
    __shared__ int ssel[32];
    const int tid = threadIdx.x;
    const int p0 = blockIdx.x * 32;
    const int h = blockIdx.y;

    // load K head-slices for both sels: 2*32*64 floats = 1024 float4s
#pragma unroll
    for (int t = 0; t < 4; t++) {
        int e = tid + t * 256;      // 0..1023
        int sel = e >> 9, slot = (e >> 4) & 31, f4 = e & 15;
        float4 v = *(const float4*)(&g_kproj[sel][slot][h * 64 + f4 * 4]);
        Ks[sel][slot][f4 * 4 + 0] = v.x; Ks[sel][slot][f4 * 4 + 1] = v.y;
        Ks[sel][slot][f4 * 4 + 2] = v.z; Ks[sel][slot][f4 * 4 + 3] = v.w;
    }
    // load q slices: 32 pos x 64 = 512 float4s
#pragma unroll
    for (int t = 0; t < 2; t++) {
        int e = tid + t * 256;
        int pos = e >> 4, f4 = e & 15;
        float4 v = *(const float4*)(&g_q[(size_t)(p0 + pos) * DDIM + h * 64 + f4 * 4]);
        qs[pos][f4 * 4 + 0] = v.x; qs[pos][f4 * 4 + 1] = v.y;
        qs[pos][f4 * 4 + 2] = v.z; qs[pos][f4 * 4 + 3] = v.w;
    }
    if (tid < 32) ssel[tid] = g_sign[p0 + tid];
    __syncthreads();

    const int w = tid >> 5, lane = tid & 31;
#pragma unroll
    for (int pi = 0; pi < 4; pi++) {
        int pos = w * 4 + pi;
        int sel = ssel[pos];
        const float* kr = &Ks[sel][lane][0];
        const float* qr = &qs[pos][0];
        float s = 0.f;
#pragma unroll
        for (int k = 0; k < 64; k++) s = fmaf(qr[k], kr[k], s);
        s *= 0.125f;
        float mx = s;
#pragma unroll
        for (int o = 16; o > 0; o >>= 1)
            mx = fmaxf(mx, __shfl_xor_sync(0xffffffffu, mx, o));
        float e = expf(s - mx);
        float sm = e;
#pragma unroll
        for (int o = 16; o > 0; o >>= 1)
            sm += __shfl_xor_sync(0xffffffffu, sm, o);
        g_p[((size_t)(p0 + pos) * NHEAD + h) * KSEL + lane] = e / sm;
    }
}

// ---------------------------------------------------------------------------
// ctx: grid (32 posblocks of 64, 16 heads), block 256.
// thread: e = tid&63, pq = tid>>6; handles 16 positions {pq + 4j}.
// ---------------------------------------------------------------------------
__global__ void __launch_bounds__(256) ctx_kernel() {
    __shared__ float Vs[2][32][68];
    __shared__ float ps[64][33];
    __shared__ int ssel[64];
    const int tid = threadIdx.x;
    const int p0 = blockIdx.x * 64;
    const int h = blockIdx.y;

    // load V head-slices for both sels: 1024 float4s
#pragma unroll
    for (int t = 0; t < 4; t++) {
        int e = tid + t * 256;
        int sel = e >> 9, slot = (e >> 4) & 31, f4 = e & 15;
        float4 v = *(const float4*)(&g_vproj[sel][slot][h * 64 + f4 * 4]);
        Vs[sel][slot][f4 * 4 + 0] = v.x; Vs[sel][slot][f4 * 4 + 1] = v.y;
        Vs[sel][slot][f4 * 4 + 2] = v.z; Vs[sel][slot][f4 * 4 + 3] = v.w;
    }
#pragma unroll
    for (int t = 0; t < 2; t++) {
        int e = tid + t * 256;      // 0..511 -> (pos, 8-chunk of 4)
        int pos = e >> 3, f4 = e & 7;
        float4 v = *(const float4*)(&g_p[((size_t)(p0 + pos) * NHEAD + h) * KSEL + f4 * 4]);
        ps[pos][f4 * 4 + 0] = v.x; ps[pos][f4 * 4 + 1] = v.y;
        ps[pos][f4 * 4 + 2] = v.z; ps[pos][f4 * 4 + 3] = v.w;
    }
    if (tid < 64) ssel[tid] = g_sign[p0 + tid];
    __syncthreads();

    const int e = tid & 63, pq = tid >> 6;
    float acc[16];
#pragma unroll
    for (int j = 0; j < 16; j++) acc[j] = 0.f;
#pragma unroll
    for (int slot = 0; slot < 32; slot++) {
        float v0 = Vs[0][slot][e];
        float v1 = Vs[1][slot][e];
#pragma unroll
        for (int j = 0; j < 16; j++) {
            int pos = pq + j * 4;
            float v = ssel[pos] ? v1 : v0;
            acc[j] = fmaf(ps[pos][slot], v, acc[j]);
        }
    }
#pragma unroll
    for (int j = 0; j < 16; j++) {
        int pos = pq + j * 4;
        g_ctx[(size_t)(p0 + pos) * DDIM + h * 64 + e] = acc[j];
    }
}

// ---------------------------------------------------------------------------
// avg_attn + sel_idx outputs. grid 256: 8 pos per block.
// ---------------------------------------------------------------------------
__global__ void __launch_bounds__(256) avgsel_kernel(float* __restrict__ out_attn,
                                                     float* __restrict__ out_selidx) {
    const int tid = threadIdx.x;
    const int pos = blockIdx.x * 8 + (tid >> 5);
    const int slot = tid & 31;
    float s = 0.f;
#pragma unroll
    for (int hh = 0; hh < NHEAD; hh++)
        s += g_p[((size_t)pos * NHEAD + hh) * KSEL + slot];
    if (out_attn)
        out_attn[(size_t)pos * KSEL + slot] = s * (1.f / NHEAD);
    if (out_selidx)
        out_selidx[(size_t)pos * KSEL + slot] = (float)g_sel[g_sign[pos]][slot];
}

// ---------------------------------------------------------------------------
// LayerNorm in-place
// ---------------------------------------------------------------------------
__global__ void __launch_bounds__(256) ln_kernel(float* __restrict__ io,
                                                 const float* __restrict__ gamma,
                                                 const float* __restrict__ beta) {
    int row = blockIdx.x;
    float4* p = reinterpret_cast<float4*>(io + (size_t)row * DDIM);
    float4 v = p[threadIdx.x];
    float s  = (v.x + v.y) + (v.z + v.w);
    float ss = v.x * v.x + v.y * v.y + v.z * v.z + v.w * v.w;
    __shared__ float r1[8], r2[8];
    __shared__ float fmu, frs;
    int lane = threadIdx.x & 31, w = threadIdx.x >> 5;
#pragma unroll
    for (int o = 16; o > 0; o >>= 1) {
        s  += __shfl_xor_sync(0xffffffffu, s, o);
        ss += __shfl_xor_sync(0xffffffffu, ss, o);
    }
    if (lane == 0) { r1[w] = s; r2[w] = ss; }
    __syncthreads();
    if (threadIdx.x == 0) {
        float ts = 0.f, tss = 0.f;
#pragma unroll
        for (int i = 0; i < 8; i++) { ts += r1[i]; tss += r2[i]; }
        float mu  = ts * (1.f / 1024.f);
        float var = tss * (1.f / 1024.f) - mu * mu;
        fmu = mu;
        frs = rsqrtf(var + 1e-5f);
    }
    __syncthreads();
    float mu = fmu, rstd = frs;
    const float4 g = reinterpret_cast<const float4*>(gamma)[threadIdx.x];
    const float4 b = reinterpret_cast<const float4*>(beta)[threadIdx.x];
    v.x = (v.x - mu) * rstd * g.x + b.x;
    v.y = (v.y - mu) * rstd * g.y + b.y;
    v.z = (v.z - mu) * rstd * g.z + b.z;
    v.w = (v.w - mu) * rstd * g.w + b.w;
    p[threadIdx.x] = v;
}

// ---------------------------------------------------------------------------
extern "C" void kernel_launch(void* const* d_in, const int* in_sizes, int n_in,
                              void* d_out, int out_size) {
    const float* X     = (const float*)d_in[0];
    const float* keys  = (const float*)d_in[1];
    const float* vals  = (const float*)d_in[2];
    const float* Wq    = (const float*)d_in[3];
    const float* Wk    = (const float*)d_in[4];
    const float* Wv    = (const float*)d_in[5];
    const float* Wo    = (const float*)d_in[6];
    const float* bo    = (const float*)d_in[7];
    const float* gamma = (const float*)d_in[8];
    const float* beta  = (const float*)d_in[9];

    float* out = (float*)d_out;
    float* out_attn = nullptr;
    float* out_sel  = nullptr;
    const long long base = (long long)BN_POS * DDIM;
    if ((long long)out_size >= base + (long long)BN_POS * KSEL)
        out_attn = out + base;
    if ((long long)out_size >= base + 2LL * BN_POS * KSEL)
        out_sel = out + base + (long long)BN_POS * KSEL;

    void *pq = nullptr, *pctx = nullptr, *pAs = nullptr, *pWs = nullptr;
    cudaGetSymbolAddress(&pq, g_q);
    cudaGetSymbolAddress(&pctx, g_ctx);
    cudaGetSymbolAddress(&pAs, g_As);
    cudaGetSymbolAddress(&pWs, g_Ws);
    __nv_bfloat16* As = (__nv_bfloat16*)pAs;
    __nv_bfloat16* Ws0 = (__nv_bfloat16*)pWs;
    __nv_bfloat16* Ws1 = Ws0 + (size_t)DDIM * GK;

    cudaFuncSetAttribute(gemm_mma_kernel,
                         cudaFuncAttributeMaxDynamicSharedMemorySize, GEMM_SMEM);

    // side stream + fork/join events (created once; capture-legal pattern)
    static cudaStream_t s2 = nullptr;
    static cudaEvent_t evFork = nullptr, evJoin = nullptr;
    if (!s2) {
        cudaStreamCreateWithFlags(&s2, cudaStreamNonBlocking);
        cudaEventCreateWithFlags(&evFork, cudaEventDisableTiming);
        cudaEventCreateWithFlags(&evJoin, cudaEventDisableTiming);
    }

    // fork side chain off the main (capture-origin) stream
    cudaEventRecord(evFork, 0);
    cudaStreamWaitEvent(s2, evFork, 0);

    // ---- side stream: selection + kvproj + sign (independent of q-proj) ----
    wbar_kernel<<<dim3(8, 32), 128, 0, s2>>>(Wq);
    qm_sign_kernel<<<BN_POS / 8, 256, 0, s2>>>(X);
    compute_c_kernel<<<MDIM / 8, 256, 0, s2>>>(keys);
    select_kernel<<<2, 1024, 0, s2>>>();
    kvproj_kernel<<<dim3(16, 2, 2), 256, 0, s2>>>(keys, vals, Wk, Wv);
    cudaEventRecord(evJoin, s2);

    // ---- main stream: splits + q projection ----
    fused_split_kernel<<<4096, 256>>>(Wq, Wo, X, Ws0, Ws1, As);
    gemm_mma_kernel<<<dim3(8, 16), 256, GEMM_SMEM>>>(As, Ws0, (float*)pq, nullptr);

    // join: attention needs q (main) + sign/kproj/vproj/sel (side)
    cudaStreamWaitEvent(0, evJoin, 0);

    scores_kernel<<<dim3(BN_POS / 32, NHEAD), 256>>>();
    ctx_kernel<<<dim3(BN_POS / 64, NHEAD), 256>>>();
    avgsel_kernel<<<BN_POS / 8, 256>>>(out_attn, out_sel);
    // o-projection + layernorm
    split_kernel<<<(BN_POS * DDIM) / 1024, 256>>>((const float*)pctx, As, 1);
    gemm_mma_kernel<<<dim3(8, 16), 256, GEMM_SMEM>>>(As, Ws1, out, bo);
    ln_kernel<<<BN_POS, 256>>>(out, gamma, beta);
}